// round 1
// baseline (speedup 1.0000x reference)
#include <cuda_runtime.h>
#include <cuda_bf16.h>
#include <math.h>

#define SQ   2048
#define EE   2048
#define HH   16
#define QLR  1536
#define KLR  512
#define DNN  128
#define DRR  64
#define DVV  128
#define DQQ  192   // DN + DR

// -------- scratch (device globals; no allocation allowed) --------
__device__ float g_qa  [SQ * QLR];          // x @ w_q_a, then rmsnormed in place
__device__ float g_q   [SQ * HH * DQQ];     // q_a @ w_q_b, rope applied in place
__device__ float g_ckv [SQ * (KLR + DRR)];  // x @ w_kv_a
__device__ float g_ckvn[SQ * KLR];          // rmsnorm(c_kv)
__device__ float g_kv  [SQ * HH * (DNN + DVV)];
__device__ float g_kpe [SQ * DRR];          // roped k_pe
__device__ float g_o   [SQ * HH * DVV];     // attention output

// ======================= SGEMM 128x128x8, 8x8 micro =======================
// M fixed = 2048 (mult of 128). K mult of 8. N mult of 4 (bounds-checked).
__global__ __launch_bounds__(256) void sgemm128(const float* __restrict__ A,
                                                const float* __restrict__ B,
                                                float* __restrict__ C,
                                                int N, int K) {
    __shared__ float As[8][128];
    __shared__ float Bs[8][128];
    const int tid = threadIdx.x;
    const int tx = tid & 15, ty = tid >> 4;
    const int bm = blockIdx.y * 128, bn = blockIdx.x * 128;

    float acc[8][8];
#pragma unroll
    for (int i = 0; i < 8; i++)
#pragma unroll
        for (int j = 0; j < 8; j++) acc[i][j] = 0.f;

    const int arow = tid >> 1, acol4 = (tid & 1) * 4;
    const int brow = tid >> 5, bcol4 = (tid & 31) * 4;

    for (int k0 = 0; k0 < K; k0 += 8) {
        // A tile: always in-bounds (M=2048, K mult of 8)
        float4 av = *(const float4*)&A[(size_t)(bm + arow) * K + k0 + acol4];
        As[acol4 + 0][arow] = av.x;
        As[acol4 + 1][arow] = av.y;
        As[acol4 + 2][arow] = av.z;
        As[acol4 + 3][arow] = av.w;

        // B tile: bounds-checked in N
        int gn = bn + bcol4;
        float4 bv;
        if (gn + 3 < N) {
            bv = *(const float4*)&B[(size_t)(k0 + brow) * N + gn];
        } else {
            const float* brp = &B[(size_t)(k0 + brow) * N];
            bv.x = (gn + 0 < N) ? brp[gn + 0] : 0.f;
            bv.y = (gn + 1 < N) ? brp[gn + 1] : 0.f;
            bv.z = (gn + 2 < N) ? brp[gn + 2] : 0.f;
            bv.w = (gn + 3 < N) ? brp[gn + 3] : 0.f;
        }
        *(float4*)&Bs[brow][bcol4] = bv;
        __syncthreads();

#pragma unroll
        for (int k = 0; k < 8; k++) {
            float4 a0 = *(const float4*)&As[k][ty * 8];
            float4 a1 = *(const float4*)&As[k][ty * 8 + 4];
            float4 b0 = *(const float4*)&Bs[k][tx * 8];
            float4 b1 = *(const float4*)&Bs[k][tx * 8 + 4];
            float a[8] = {a0.x, a0.y, a0.z, a0.w, a1.x, a1.y, a1.z, a1.w};
            float b[8] = {b0.x, b0.y, b0.z, b0.w, b1.x, b1.y, b1.z, b1.w};
#pragma unroll
            for (int i = 0; i < 8; i++)
#pragma unroll
                for (int j = 0; j < 8; j++) acc[i][j] += a[i] * b[j];
        }
        __syncthreads();
    }

#pragma unroll
    for (int i = 0; i < 8; i++) {
        int m = bm + ty * 8 + i;
#pragma unroll
        for (int j = 0; j < 8; j++) {
            int n = bn + tx * 8 + j;
            if (n < N) C[(size_t)m * N + n] = acc[i][j];
        }
    }
}

// ======================= RMSNorm (row per block) =======================
__global__ void rmsnorm_kernel(const float* __restrict__ in,
                               const float* __restrict__ w,
                               float* __restrict__ out,
                               int D, int in_stride, int out_stride) {
    const int row = blockIdx.x;
    const float* x = in + (size_t)row * in_stride;
    float* y = out + (size_t)row * out_stride;

    float ss = 0.f;
    for (int i = threadIdx.x; i < D; i += blockDim.x) {
        float v = x[i];
        ss += v * v;
    }
#pragma unroll
    for (int m = 16; m; m >>= 1) ss += __shfl_xor_sync(0xffffffffu, ss, m);

    __shared__ float wsum[8];
    if ((threadIdx.x & 31) == 0) wsum[threadIdx.x >> 5] = ss;
    __syncthreads();
    float tot = 0.f;
#pragma unroll
    for (int i = 0; i < 8; i++) tot += wsum[i];
    float scale = rsqrtf(tot / (float)D + 1e-6f);
    for (int i = threadIdx.x; i < D; i += blockDim.x) y[i] = x[i] * scale * w[i];
}

// ======================= RoPE =======================
// Reference permutes: new[j]=orig[2j], new[32+j]=orig[2j+1], then rotate-half.
// out[j]    = orig[2j]*cos(t*f_j)   - orig[2j+1]*sin(t*f_j)
// out[32+j] = orig[2j+1]*cos(t*f_j) + orig[2j]*sin(t*f_j),  f_j = 10000^(-j/32)
#define LOG2_10000_OVER_32 0.4152410118609203f

__global__ void rope_q_kernel(float* __restrict__ q) {
    int w = (blockIdx.x * blockDim.x + threadIdx.x) >> 5;
    int lane = threadIdx.x & 31;
    if (w >= SQ * HH) return;
    int s = w >> 4, h = w & 15;
    float* base = q + (size_t)s * (HH * DQQ) + h * DQQ + DNN;
    float x0 = base[2 * lane];
    float x1 = base[2 * lane + 1];
    float invf = exp2f(-(float)lane * LOG2_10000_OVER_32);
    float ang = (float)s * invf;
    float sn, cs;
    sincosf(ang, &sn, &cs);
    float o0 = x0 * cs - x1 * sn;
    float o1 = x1 * cs + x0 * sn;
    __syncwarp();
    base[lane] = o0;
    base[32 + lane] = o1;
}

__global__ void rope_k_kernel(const float* __restrict__ ckv, float* __restrict__ kpe) {
    int w = (blockIdx.x * blockDim.x + threadIdx.x) >> 5;
    int lane = threadIdx.x & 31;
    if (w >= SQ) return;
    const float* base = ckv + (size_t)w * (KLR + DRR) + KLR;
    float x0 = base[2 * lane];
    float x1 = base[2 * lane + 1];
    float invf = exp2f(-(float)lane * LOG2_10000_OVER_32);
    float ang = (float)w * invf;
    float sn, cs;
    sincosf(ang, &sn, &cs);
    kpe[(size_t)w * DRR + lane]      = x0 * cs - x1 * sn;
    kpe[(size_t)w * DRR + 32 + lane] = x1 * cs + x0 * sn;
}

// ======================= Flash attention =======================
// BM=BN=64, 256 threads. Thread (tx,ty) owns score rows 4ty..+3, score cols
// 4tx..+3, and O cols {tx+16j}. Online softmax. d_qk=192, d_v=128.
#define FL_QT_STRIDE 68
#define FL_V_STRIDE  136
#define FL_SMEM_FLOATS (192 * 68 /*Qt*/ + 192 * 68 /*Kt*/ + 64 * 136 /*Vs*/ + 64 * 68 /*Ps*/)

__global__ __launch_bounds__(256) void flash_kernel(const float* __restrict__ q,
                                                    const float* __restrict__ kv,
                                                    const float* __restrict__ kpe,
                                                    float* __restrict__ o) {
    extern __shared__ float sm[];
    float* Qt = sm;                   // [192][68] d-major
    float* Kt = Qt + 192 * 68;        // [192][68] d-major
    float* Vs = Kt + 192 * 68;        // [64][136] row-major
    float* Ps = Vs + 64 * 136;        // [64][68]

    const int h = blockIdx.y;
    const int qb = blockIdx.x;
    const int tid = threadIdx.x;
    const int tx = tid & 15, ty = tid >> 4;
    const int q0 = qb * 64;
    const float scale = 0.07216878364870322f; // 1/sqrt(192)

    // load Q (roped) transposed: Qt[d][r]
    for (int i = tid; i < 64 * 192; i += 256) {
        int r = i / 192, d = i % 192;
        Qt[d * FL_QT_STRIDE + r] = q[(size_t)(q0 + r) * (HH * DQQ) + h * DQQ + d];
    }

    float acc[4][8];
    float m_i[4], l_i[4];
#pragma unroll
    for (int i = 0; i < 4; i++) {
        m_i[i] = -1e30f;
        l_i[i] = 0.f;
#pragma unroll
        for (int j = 0; j < 8; j++) acc[i][j] = 0.f;
    }

    for (int kb = 0; kb <= qb; kb++) {
        const int k0 = kb * 64;
        __syncthreads(); // protect Kt/Vs/Ps from prior phase reads (also 1st iter no-op)

        // load K transposed (nope from kv, pe from kpe)
        for (int i = tid; i < 64 * 192; i += 256) {
            int r = i / 192, d = i % 192;
            float v = (d < DNN)
                        ? kv[(size_t)(k0 + r) * (HH * 256) + h * 256 + d]
                        : kpe[(size_t)(k0 + r) * DRR + (d - DNN)];
            Kt[d * FL_QT_STRIDE + r] = v;
        }
        // load V row-major
        for (int i = tid; i < 64 * 128; i += 256) {
            int r = i / 128, d = i % 128;
            Vs[r * FL_V_STRIDE + d] = kv[(size_t)(k0 + r) * (HH * 256) + h * 256 + DNN + d];
        }
        __syncthreads();

        // scores 4x4
        float sc[4][4];
#pragma unroll
        for (int i = 0; i < 4; i++)
#pragma unroll
            for (int j = 0; j < 4; j++) sc[i][j] = 0.f;

        for (int d = 0; d < 192; d++) {
            float4 a = *(const float4*)(Qt + d * FL_QT_STRIDE + 4 * ty);
            float4 b = *(const float4*)(Kt + d * FL_QT_STRIDE + 4 * tx);
            float av[4] = {a.x, a.y, a.z, a.w};
            float bv[4] = {b.x, b.y, b.z, b.w};
#pragma unroll
            for (int i = 0; i < 4; i++)
#pragma unroll
                for (int j = 0; j < 4; j++) sc[i][j] += av[i] * bv[j];
        }

        // mask+scale, online softmax, P store
#pragma unroll
        for (int i = 0; i < 4; i++) {
            int qi = q0 + 4 * ty + i;
#pragma unroll
            for (int j = 0; j < 4; j++) {
                int kj = k0 + 4 * tx + j;
                sc[i][j] = (kj <= qi) ? sc[i][j] * scale : -1e30f;
            }
            float mloc = fmaxf(fmaxf(sc[i][0], sc[i][1]), fmaxf(sc[i][2], sc[i][3]));
#pragma unroll
            for (int msk = 8; msk; msk >>= 1)
                mloc = fmaxf(mloc, __shfl_xor_sync(0xffffffffu, mloc, msk));
            float m_new = fmaxf(m_i[i], mloc);
            float alpha = expf(m_i[i] - m_new);
            float rsum = 0.f;
#pragma unroll
            for (int j = 0; j < 4; j++) {
                float e = expf(sc[i][j] - m_new);
                sc[i][j] = e;
                rsum += e;
            }
#pragma unroll
            for (int msk = 8; msk; msk >>= 1)
                rsum += __shfl_xor_sync(0xffffffffu, rsum, msk);
            l_i[i] = l_i[i] * alpha + rsum;
            m_i[i] = m_new;
#pragma unroll
            for (int j = 0; j < 8; j++) acc[i][j] *= alpha;
#pragma unroll
            for (int j = 0; j < 4; j++)
                Ps[(4 * ty + i) * FL_QT_STRIDE + 4 * tx + j] = sc[i][j];
        }
        __syncthreads();

        // O += P @ V
        for (int kk = 0; kk < 64; kk++) {
            float p0 = Ps[(4 * ty + 0) * FL_QT_STRIDE + kk];
            float p1 = Ps[(4 * ty + 1) * FL_QT_STRIDE + kk];
            float p2 = Ps[(4 * ty + 2) * FL_QT_STRIDE + kk];
            float p3 = Ps[(4 * ty + 3) * FL_QT_STRIDE + kk];
#pragma unroll
            for (int j = 0; j < 8; j++) {
                float vv = Vs[kk * FL_V_STRIDE + tx + 16 * j];
                acc[0][j] += p0 * vv;
                acc[1][j] += p1 * vv;
                acc[2][j] += p2 * vv;
                acc[3][j] += p3 * vv;
            }
        }
    }

    // epilogue: normalize, write o[s][h*128 + col]
#pragma unroll
    for (int i = 0; i < 4; i++) {
        float inv = 1.f / l_i[i];
        int row = q0 + 4 * ty + i;
#pragma unroll
        for (int j = 0; j < 8; j++) {
            o[(size_t)row * (HH * DVV) + h * DVV + tx + 16 * j] = acc[i][j] * inv;
        }
    }
}

// ======================= launch =======================
extern "C" void kernel_launch(void* const* d_in, const int* in_sizes, int n_in,
                              void* d_out, int out_size) {
    const float* x       = (const float*)d_in[0];
    const float* w_q_a   = (const float*)d_in[1];
    const float* q_a_ln  = (const float*)d_in[2];
    const float* w_q_b   = (const float*)d_in[3];
    const float* w_kv_a  = (const float*)d_in[4];
    const float* kv_a_ln = (const float*)d_in[5];
    const float* w_kv_b  = (const float*)d_in[6];
    const float* w_out   = (const float*)d_in[7];
    float* out = (float*)d_out;

    float *qa, *qbuf, *ckv, *ckvn, *kvb, *kpe, *obuf;
    cudaGetSymbolAddress((void**)&qa,   g_qa);
    cudaGetSymbolAddress((void**)&qbuf, g_q);
    cudaGetSymbolAddress((void**)&ckv,  g_ckv);
    cudaGetSymbolAddress((void**)&ckvn, g_ckvn);
    cudaGetSymbolAddress((void**)&kvb,  g_kv);
    cudaGetSymbolAddress((void**)&kpe,  g_kpe);
    cudaGetSymbolAddress((void**)&obuf, g_o);

    const int smem_fl = FL_SMEM_FLOATS * (int)sizeof(float);
    cudaFuncSetAttribute(flash_kernel, cudaFuncAttributeMaxDynamicSharedMemorySize, smem_fl);

    dim3 blk(256);

    // 1. q_a = x @ w_q_a   [2048,2048]x[2048,1536]
    sgemm128<<<dim3(QLR / 128, SQ / 128), blk>>>(x, w_q_a, qa, QLR, EE);
    // 2. rmsnorm q_a (in place)
    rmsnorm_kernel<<<SQ, blk>>>(qa, q_a_ln, qa, QLR, QLR, QLR);
    // 3. q = q_a @ w_q_b   [2048,1536]x[1536,3072]
    sgemm128<<<dim3((HH * DQQ) / 128, SQ / 128), blk>>>(qa, w_q_b, qbuf, HH * DQQ, QLR);
    // 4. ckv = x @ w_kv_a  [2048,2048]x[2048,576]
    sgemm128<<<dim3((KLR + DRR + 127) / 128, SQ / 128), blk>>>(x, w_kv_a, ckv, KLR + DRR, EE);
    // 5. rmsnorm c_kv -> ckvn
    rmsnorm_kernel<<<SQ, blk>>>(ckv, kv_a_ln, ckvn, KLR, KLR + DRR, KLR);
    // 6. kv = ckvn @ w_kv_b [2048,512]x[512,4096]
    sgemm128<<<dim3((HH * 256) / 128, SQ / 128), blk>>>(ckvn, w_kv_b, kvb, HH * 256, KLR);
    // 7. rope
    rope_q_kernel<<<(SQ * HH * 32) / 256, blk>>>(qbuf);
    rope_k_kernel<<<(SQ * 32 + 255) / 256, blk>>>(ckv, kpe);
    // 8. attention
    flash_kernel<<<dim3(SQ / 64, HH), blk, smem_fl>>>(qbuf, kvb, kpe, obuf);
    // 9. out = o @ w_out [2048,2048]x[2048,2048]
    sgemm128<<<dim3(EE / 128, SQ / 128), blk>>>(obuf, w_out, out, EE, EE);
}

// round 2
// speedup vs baseline: 1.4504x; 1.4504x over previous
#include <cuda_runtime.h>
#include <cuda_bf16.h>
#include <math.h>

#define SQ   2048
#define EE   2048
#define HH   16
#define QLR  1536
#define KLR  512
#define DNN  128
#define DRR  64
#define DVV  128
#define DQQ  192   // DN + DR

// -------- scratch (device globals; no allocation allowed) --------
__device__ float g_qa  [SQ * QLR];
__device__ float g_q   [SQ * HH * DQQ];
__device__ float g_ckv [SQ * (KLR + DRR)];
__device__ float g_ckvn[SQ * KLR];
__device__ float g_kv  [SQ * HH * (DNN + DVV)];
__device__ float g_kpe [SQ * DRR];
__device__ float g_o   [SQ * HH * DVV];

// bf16 hi/lo conversion scratch (reused across stages; stream order serializes)
__device__ __nv_bfloat16 g_Ah[SQ * EE];
__device__ __nv_bfloat16 g_Al[SQ * EE];
__device__ __nv_bfloat16 g_Bh[QLR * 3072];
__device__ __nv_bfloat16 g_Bl[QLR * 3072];

// ======================= fp32 -> bf16 hi/lo split =======================
__global__ void conv_split(const float* __restrict__ in,
                           __nv_bfloat16* __restrict__ hi,
                           __nv_bfloat16* __restrict__ lo, int n) {
    int i = (blockIdx.x * blockDim.x + threadIdx.x) * 4;
    if (i >= n) return;
    float4 v = *(const float4*)(in + i);
    __nv_bfloat16 h[4], l[4];
    h[0] = __float2bfloat16(v.x); l[0] = __float2bfloat16(v.x - __bfloat162float(h[0]));
    h[1] = __float2bfloat16(v.y); l[1] = __float2bfloat16(v.y - __bfloat162float(h[1]));
    h[2] = __float2bfloat16(v.z); l[2] = __float2bfloat16(v.z - __bfloat162float(h[2]));
    h[3] = __float2bfloat16(v.w); l[3] = __float2bfloat16(v.w - __bfloat162float(h[3]));
    *(ushort4*)(hi + i) = *(ushort4*)h;
    *(ushort4*)(lo + i) = *(ushort4*)l;
}

// ======================= bf16x3 MMA GEMM 128x128x32 =======================
// C[M,N] = A[M,K] @ B[K,N] in ~fp32 precision via Ah*Bh + Ah*Bl + Al*Bh.
// M=2048 (mult 128), K mult of 32, N mult of 8 (bounds-checked).
#define ASTRIDE 40
#define BSTRIDE 136

__device__ __forceinline__ unsigned pack2(unsigned short a, unsigned short b) {
    return (unsigned)a | ((unsigned)b << 16);
}

__device__ __forceinline__ void mma_bf16(float* d, const unsigned* a, const unsigned* b) {
    asm volatile(
        "mma.sync.aligned.m16n8k16.row.col.f32.bf16.bf16.f32 "
        "{%0,%1,%2,%3}, {%4,%5,%6,%7}, {%8,%9}, {%0,%1,%2,%3};\n"
        : "+f"(d[0]), "+f"(d[1]), "+f"(d[2]), "+f"(d[3])
        : "r"(a[0]), "r"(a[1]), "r"(a[2]), "r"(a[3]), "r"(b[0]), "r"(b[1]));
}

__global__ __launch_bounds__(256, 2) void bgemm(const __nv_bfloat16* __restrict__ Ahg,
                                                const __nv_bfloat16* __restrict__ Alg,
                                                const __nv_bfloat16* __restrict__ Bhg,
                                                const __nv_bfloat16* __restrict__ Blg,
                                                float* __restrict__ C,
                                                int N, int K) {
    __shared__ unsigned short sAh[128 * ASTRIDE];
    __shared__ unsigned short sAl[128 * ASTRIDE];
    __shared__ unsigned short sBh[32 * BSTRIDE];
    __shared__ unsigned short sBl[32 * BSTRIDE];

    const int tid  = threadIdx.x;
    const int warp = tid >> 5, lane = tid & 31;
    const int wm = warp >> 2, wn = warp & 3;     // 2x4 warp grid
    const int g = lane >> 2, t = lane & 3;
    const int bm = blockIdx.y * 128, bn = blockIdx.x * 128;

    float acc[4][4][4];
#pragma unroll
    for (int mt = 0; mt < 4; mt++)
#pragma unroll
        for (int nt = 0; nt < 4; nt++)
#pragma unroll
            for (int k = 0; k < 4; k++) acc[mt][nt][k] = 0.f;

    for (int k0 = 0; k0 < K; k0 += 32) {
        // A tiles: 128x32, 2 x uint4 per thread per matrix
#pragma unroll
        for (int i = 0; i < 2; i++) {
            int u = tid + 256 * i;
            int r = u >> 2, sg = (u & 3) * 8;
            size_t go = (size_t)(bm + r) * K + k0 + sg;
            *(uint4*)&sAh[r * ASTRIDE + sg] = *(const uint4*)(Ahg + go);
            *(uint4*)&sAl[r * ASTRIDE + sg] = *(const uint4*)(Alg + go);
        }
        // B tiles: 32x128, bounds-checked in N
#pragma unroll
        for (int i = 0; i < 2; i++) {
            int u = tid + 256 * i;
            int r = u >> 4, sg = (u & 15) * 8;
            int gn = bn + sg;
            if (gn + 7 < N) {
                size_t go = (size_t)(k0 + r) * N + gn;
                *(uint4*)&sBh[r * BSTRIDE + sg] = *(const uint4*)(Bhg + go);
                *(uint4*)&sBl[r * BSTRIDE + sg] = *(const uint4*)(Blg + go);
            } else {
                const __nv_bfloat16* bh = Bhg + (size_t)(k0 + r) * N;
                const __nv_bfloat16* bl = Blg + (size_t)(k0 + r) * N;
                __nv_bfloat16 z = __float2bfloat16(0.f);
#pragma unroll
                for (int j = 0; j < 8; j++) {
                    __nv_bfloat16 vh = (gn + j < N) ? bh[gn + j] : z;
                    __nv_bfloat16 vl = (gn + j < N) ? bl[gn + j] : z;
                    sBh[r * BSTRIDE + sg + j] = *(unsigned short*)&vh;
                    sBl[r * BSTRIDE + sg + j] = *(unsigned short*)&vl;
                }
            }
        }
        __syncthreads();

#pragma unroll
        for (int kk = 0; kk < 32; kk += 16) {
            unsigned bh[4][2], bl[4][2];
#pragma unroll
            for (int nt = 0; nt < 4; nt++) {
                int cn = wn * 32 + nt * 8 + g;
                int r0 = kk + 2 * t;
                bh[nt][0] = pack2(sBh[r0 * BSTRIDE + cn], sBh[(r0 + 1) * BSTRIDE + cn]);
                bh[nt][1] = pack2(sBh[(r0 + 8) * BSTRIDE + cn], sBh[(r0 + 9) * BSTRIDE + cn]);
                bl[nt][0] = pack2(sBl[r0 * BSTRIDE + cn], sBl[(r0 + 1) * BSTRIDE + cn]);
                bl[nt][1] = pack2(sBl[(r0 + 8) * BSTRIDE + cn], sBl[(r0 + 9) * BSTRIDE + cn]);
            }
#pragma unroll
            for (int mt = 0; mt < 4; mt++) {
                int r0 = wm * 64 + mt * 16 + g;
                int c0 = kk + t * 2;
                unsigned ah[4], al[4];
                ah[0] = *(const unsigned*)&sAh[r0 * ASTRIDE + c0];
                ah[1] = *(const unsigned*)&sAh[(r0 + 8) * ASTRIDE + c0];
                ah[2] = *(const unsigned*)&sAh[r0 * ASTRIDE + c0 + 8];
                ah[3] = *(const unsigned*)&sAh[(r0 + 8) * ASTRIDE + c0 + 8];
                al[0] = *(const unsigned*)&sAl[r0 * ASTRIDE + c0];
                al[1] = *(const unsigned*)&sAl[(r0 + 8) * ASTRIDE + c0];
                al[2] = *(const unsigned*)&sAl[r0 * ASTRIDE + c0 + 8];
                al[3] = *(const unsigned*)&sAl[(r0 + 8) * ASTRIDE + c0 + 8];
#pragma unroll
                for (int nt = 0; nt < 4; nt++) {
                    mma_bf16(acc[mt][nt], ah, bh[nt]);
                    mma_bf16(acc[mt][nt], ah, bl[nt]);
                    mma_bf16(acc[mt][nt], al, bh[nt]);
                }
            }
        }
        __syncthreads();
    }

    // store C
#pragma unroll
    for (int mt = 0; mt < 4; mt++) {
        int row = bm + wm * 64 + mt * 16 + g;
#pragma unroll
        for (int nt = 0; nt < 4; nt++) {
            int col = bn + wn * 32 + nt * 8 + 2 * t;
            if (col < N) {
                *(float2*)&C[(size_t)row * N + col] =
                    make_float2(acc[mt][nt][0], acc[mt][nt][1]);
                *(float2*)&C[(size_t)(row + 8) * N + col] =
                    make_float2(acc[mt][nt][2], acc[mt][nt][3]);
            }
        }
    }
}

// ======================= RMSNorm (row per block) =======================
__global__ void rmsnorm_kernel(const float* __restrict__ in,
                               const float* __restrict__ w,
                               float* __restrict__ out,
                               int D, int in_stride, int out_stride) {
    const int row = blockIdx.x;
    const float* x = in + (size_t)row * in_stride;
    float* y = out + (size_t)row * out_stride;

    float ss = 0.f;
    for (int i = threadIdx.x; i < D; i += blockDim.x) {
        float v = x[i];
        ss += v * v;
    }
#pragma unroll
    for (int m = 16; m; m >>= 1) ss += __shfl_xor_sync(0xffffffffu, ss, m);

    __shared__ float wsum[8];
    if ((threadIdx.x & 31) == 0) wsum[threadIdx.x >> 5] = ss;
    __syncthreads();
    float tot = 0.f;
#pragma unroll
    for (int i = 0; i < 8; i++) tot += wsum[i];
    float scale = rsqrtf(tot / (float)D + 1e-6f);
    for (int i = threadIdx.x; i < D; i += blockDim.x) y[i] = x[i] * scale * w[i];
}

// ======================= RoPE =======================
#define LOG2_10000_OVER_32 0.4152410118609203f

__global__ void rope_q_kernel(float* __restrict__ q) {
    int w = (blockIdx.x * blockDim.x + threadIdx.x) >> 5;
    int lane = threadIdx.x & 31;
    if (w >= SQ * HH) return;
    int s = w >> 4, h = w & 15;
    float* base = q + (size_t)s * (HH * DQQ) + h * DQQ + DNN;
    float x0 = base[2 * lane];
    float x1 = base[2 * lane + 1];
    float invf = exp2f(-(float)lane * LOG2_10000_OVER_32);
    float ang = (float)s * invf;
    float sn, cs;
    sincosf(ang, &sn, &cs);
    float o0 = x0 * cs - x1 * sn;
    float o1 = x1 * cs + x0 * sn;
    __syncwarp();
    base[lane] = o0;
    base[32 + lane] = o1;
}

__global__ void rope_k_kernel(const float* __restrict__ ckv, float* __restrict__ kpe) {
    int w = (blockIdx.x * blockDim.x + threadIdx.x) >> 5;
    int lane = threadIdx.x & 31;
    if (w >= SQ) return;
    const float* base = ckv + (size_t)w * (KLR + DRR) + KLR;
    float x0 = base[2 * lane];
    float x1 = base[2 * lane + 1];
    float invf = exp2f(-(float)lane * LOG2_10000_OVER_32);
    float ang = (float)w * invf;
    float sn, cs;
    sincosf(ang, &sn, &cs);
    kpe[(size_t)w * DRR + lane]      = x0 * cs - x1 * sn;
    kpe[(size_t)w * DRR + 32 + lane] = x1 * cs + x0 * sn;
}

// ======================= Flash attention (fp32) =======================
#define FL_QT_STRIDE 68
#define FL_V_STRIDE  136
#define FL_SMEM_FLOATS (192 * 68 + 192 * 68 + 64 * 136 + 64 * 68)

__global__ __launch_bounds__(256) void flash_kernel(const float* __restrict__ q,
                                                    const float* __restrict__ kv,
                                                    const float* __restrict__ kpe,
                                                    float* __restrict__ o) {
    extern __shared__ float sm[];
    float* Qt = sm;
    float* Kt = Qt + 192 * 68;
    float* Vs = Kt + 192 * 68;
    float* Ps = Vs + 64 * 136;

    const int h = blockIdx.y;
    const int qb = blockIdx.x;
    const int tid = threadIdx.x;
    const int tx = tid & 15, ty = tid >> 4;
    const int q0 = qb * 64;
    const float scale = 0.07216878364870322f; // 1/sqrt(192)

    for (int i = tid; i < 64 * 192; i += 256) {
        int r = i / 192, d = i % 192;
        Qt[d * FL_QT_STRIDE + r] = q[(size_t)(q0 + r) * (HH * DQQ) + h * DQQ + d];
    }

    float acc[4][8];
    float m_i[4], l_i[4];
#pragma unroll
    for (int i = 0; i < 4; i++) {
        m_i[i] = -1e30f;
        l_i[i] = 0.f;
#pragma unroll
        for (int j = 0; j < 8; j++) acc[i][j] = 0.f;
    }

    for (int kb = 0; kb <= qb; kb++) {
        const int k0 = kb * 64;
        __syncthreads();

        for (int i = tid; i < 64 * 192; i += 256) {
            int r = i / 192, d = i % 192;
            float v = (d < DNN)
                        ? kv[(size_t)(k0 + r) * (HH * 256) + h * 256 + d]
                        : kpe[(size_t)(k0 + r) * DRR + (d - DNN)];
            Kt[d * FL_QT_STRIDE + r] = v;
        }
        for (int i = tid; i < 64 * 128; i += 256) {
            int r = i / 128, d = i % 128;
            Vs[r * FL_V_STRIDE + d] = kv[(size_t)(k0 + r) * (HH * 256) + h * 256 + DNN + d];
        }
        __syncthreads();

        float sc[4][4];
#pragma unroll
        for (int i = 0; i < 4; i++)
#pragma unroll
            for (int j = 0; j < 4; j++) sc[i][j] = 0.f;

        for (int d = 0; d < 192; d++) {
            float4 a = *(const float4*)(Qt + d * FL_QT_STRIDE + 4 * ty);
            float4 b = *(const float4*)(Kt + d * FL_QT_STRIDE + 4 * tx);
            float av[4] = {a.x, a.y, a.z, a.w};
            float bv[4] = {b.x, b.y, b.z, b.w};
#pragma unroll
            for (int i = 0; i < 4; i++)
#pragma unroll
                for (int j = 0; j < 4; j++) sc[i][j] += av[i] * bv[j];
        }

#pragma unroll
        for (int i = 0; i < 4; i++) {
            int qi = q0 + 4 * ty + i;
#pragma unroll
            for (int j = 0; j < 4; j++) {
                int kj = k0 + 4 * tx + j;
                sc[i][j] = (kj <= qi) ? sc[i][j] * scale : -1e30f;
            }
            float mloc = fmaxf(fmaxf(sc[i][0], sc[i][1]), fmaxf(sc[i][2], sc[i][3]));
#pragma unroll
            for (int msk = 8; msk; msk >>= 1)
                mloc = fmaxf(mloc, __shfl_xor_sync(0xffffffffu, mloc, msk));
            float m_new = fmaxf(m_i[i], mloc);
            float alpha = expf(m_i[i] - m_new);
            float rsum = 0.f;
#pragma unroll
            for (int j = 0; j < 4; j++) {
                float e = expf(sc[i][j] - m_new);
                sc[i][j] = e;
                rsum += e;
            }
#pragma unroll
            for (int msk = 8; msk; msk >>= 1)
                rsum += __shfl_xor_sync(0xffffffffu, rsum, msk);
            l_i[i] = l_i[i] * alpha + rsum;
            m_i[i] = m_new;
#pragma unroll
            for (int j = 0; j < 8; j++) acc[i][j] *= alpha;
#pragma unroll
            for (int j = 0; j < 4; j++)
                Ps[(4 * ty + i) * FL_QT_STRIDE + 4 * tx + j] = sc[i][j];
        }
        __syncthreads();

        for (int kk = 0; kk < 64; kk++) {
            float p0 = Ps[(4 * ty + 0) * FL_QT_STRIDE + kk];
            float p1 = Ps[(4 * ty + 1) * FL_QT_STRIDE + kk];
            float p2 = Ps[(4 * ty + 2) * FL_QT_STRIDE + kk];
            float p3 = Ps[(4 * ty + 3) * FL_QT_STRIDE + kk];
#pragma unroll
            for (int j = 0; j < 8; j++) {
                float vv = Vs[kk * FL_V_STRIDE + tx + 16 * j];
                acc[0][j] += p0 * vv;
                acc[1][j] += p1 * vv;
                acc[2][j] += p2 * vv;
                acc[3][j] += p3 * vv;
            }
        }
    }

#pragma unroll
    for (int i = 0; i < 4; i++) {
        float inv = 1.f / l_i[i];
        int row = q0 + 4 * ty + i;
#pragma unroll
        for (int j = 0; j < 8; j++) {
            o[(size_t)row * (HH * DVV) + h * DVV + tx + 16 * j] = acc[i][j] * inv;
        }
    }
}

// ======================= launch =======================
extern "C" void kernel_launch(void* const* d_in, const int* in_sizes, int n_in,
                              void* d_out, int out_size) {
    const float* x       = (const float*)d_in[0];
    const float* w_q_a   = (const float*)d_in[1];
    const float* q_a_ln  = (const float*)d_in[2];
    const float* w_q_b   = (const float*)d_in[3];
    const float* w_kv_a  = (const float*)d_in[4];
    const float* kv_a_ln = (const float*)d_in[5];
    const float* w_kv_b  = (const float*)d_in[6];
    const float* w_out   = (const float*)d_in[7];
    float* out = (float*)d_out;

    float *qa, *qbuf, *ckv, *ckvn, *kvb, *kpe, *obuf;
    __nv_bfloat16 *Ah, *Al, *Bh, *Bl;
    cudaGetSymbolAddress((void**)&qa,   g_qa);
    cudaGetSymbolAddress((void**)&qbuf, g_q);
    cudaGetSymbolAddress((void**)&ckv,  g_ckv);
    cudaGetSymbolAddress((void**)&ckvn, g_ckvn);
    cudaGetSymbolAddress((void**)&kvb,  g_kv);
    cudaGetSymbolAddress((void**)&kpe,  g_kpe);
    cudaGetSymbolAddress((void**)&obuf, g_o);
    cudaGetSymbolAddress((void**)&Ah,   g_Ah);
    cudaGetSymbolAddress((void**)&Al,   g_Al);
    cudaGetSymbolAddress((void**)&Bh,   g_Bh);
    cudaGetSymbolAddress((void**)&Bl,   g_Bl);

    const int smem_fl = FL_SMEM_FLOATS * (int)sizeof(float);
    cudaFuncSetAttribute(flash_kernel, cudaFuncAttributeMaxDynamicSharedMemorySize, smem_fl);

    dim3 blk(256);
    auto conv = [&](const float* src, __nv_bfloat16* h, __nv_bfloat16* l, int n) {
        conv_split<<<(n / 4 + 255) / 256, blk>>>(src, h, l, n);
    };

    // x -> bf16 hi/lo (used by q_a and kv_a gemms)
    conv(x, Ah, Al, SQ * EE);

    // 1. q_a = x @ w_q_a   [2048,2048]x[2048,1536]
    conv(w_q_a, Bh, Bl, EE * QLR);
    bgemm<<<dim3(QLR / 128, SQ / 128), blk>>>(Ah, Al, Bh, Bl, qa, QLR, EE);

    // 2. ckv = x @ w_kv_a  [2048,2048]x[2048,576]
    conv(w_kv_a, Bh, Bl, EE * (KLR + DRR));
    bgemm<<<dim3((KLR + DRR + 127) / 128, SQ / 128), blk>>>(Ah, Al, Bh, Bl, ckv, KLR + DRR, EE);

    // 3. rmsnorms
    rmsnorm_kernel<<<SQ, blk>>>(qa, q_a_ln, qa, QLR, QLR, QLR);
    rmsnorm_kernel<<<SQ, blk>>>(ckv, kv_a_ln, ckvn, KLR, KLR + DRR, KLR);

    // 4. q = q_a @ w_q_b   [2048,1536]x[1536,3072]
    conv(qa, Ah, Al, SQ * QLR);
    conv(w_q_b, Bh, Bl, QLR * HH * DQQ);
    bgemm<<<dim3((HH * DQQ) / 128, SQ / 128), blk>>>(Ah, Al, Bh, Bl, qbuf, HH * DQQ, QLR);

    // 5. kv = ckvn @ w_kv_b [2048,512]x[512,4096]
    conv(ckvn, Ah, Al, SQ * KLR);
    conv(w_kv_b, Bh, Bl, KLR * HH * 256);
    bgemm<<<dim3((HH * 256) / 128, SQ / 128), blk>>>(Ah, Al, Bh, Bl, kvb, HH * 256, KLR);

    // 6. rope
    rope_q_kernel<<<(SQ * HH * 32) / 256, blk>>>(qbuf);
    rope_k_kernel<<<(SQ * 32 + 255) / 256, blk>>>(ckv, kpe);

    // 7. attention
    flash_kernel<<<dim3(SQ / 64, HH), blk, smem_fl>>>(qbuf, kvb, kpe, obuf);

    // 8. out = o @ w_out [2048,2048]x[2048,2048]
    conv(obuf, Ah, Al, SQ * HH * DVV);
    conv(w_out, Bh, Bl, HH * DVV * EE);
    bgemm<<<dim3(EE / 128, SQ / 128), blk>>>(Ah, Al, Bh, Bl, out, EE, EE);
}

// round 4
// speedup vs baseline: 3.7896x; 2.6128x over previous
#include <cuda_runtime.h>
#include <cuda_bf16.h>
#include <math.h>
#include <stdint.h>

#define SQ   2048
#define EE   2048
#define HH   16
#define QLR  1536
#define KLR  512
#define DNN  128
#define DRR  64
#define DVV  128
#define DQQ  192

// -------- scratch --------
__device__ float g_qa  [SQ * QLR];
__device__ float g_q   [SQ * HH * DQQ];
__device__ float g_ckv [SQ * (KLR + DRR)];
__device__ float g_ckvn[SQ * KLR];
__device__ float g_kv  [SQ * HH * (DNN + DVV)];
__device__ float g_kpe [SQ * DRR];
__device__ float g_o   [SQ * HH * DVV];

__device__ __nv_bfloat16 g_Ah[SQ * EE];
__device__ __nv_bfloat16 g_Al[SQ * EE];
__device__ __nv_bfloat16 g_Bh[QLR * 3072];
__device__ __nv_bfloat16 g_Bl[QLR * 3072];

// ======================= helpers =======================
__device__ __forceinline__ uint32_t s2u(const void* p) {
    return (uint32_t)__cvta_generic_to_shared(p);
}
__device__ __forceinline__ void cpa(uint32_t d, const void* s) {
    asm volatile("cp.async.cg.shared.global [%0], [%1], 16;\n" :: "r"(d), "l"(s));
}
#define CP_COMMIT asm volatile("cp.async.commit_group;\n")
#define CP_WAIT0  asm volatile("cp.async.wait_group 0;\n")
#define CP_WAIT1  asm volatile("cp.async.wait_group 1;\n")

__device__ __forceinline__ void ldsm4(uint32_t a, unsigned* d) {
    asm volatile("ldmatrix.sync.aligned.m8n8.x4.shared.b16 {%0,%1,%2,%3}, [%4];\n"
        : "=r"(d[0]), "=r"(d[1]), "=r"(d[2]), "=r"(d[3]) : "r"(a));
}
__device__ __forceinline__ void ldsm2(uint32_t a, unsigned* d) {
    asm volatile("ldmatrix.sync.aligned.m8n8.x2.shared.b16 {%0,%1}, [%2];\n"
        : "=r"(d[0]), "=r"(d[1]) : "r"(a));
}
__device__ __forceinline__ void ldsm2t(uint32_t a, unsigned* d) {
    asm volatile("ldmatrix.sync.aligned.m8n8.x2.trans.shared.b16 {%0,%1}, [%2];\n"
        : "=r"(d[0]), "=r"(d[1]) : "r"(a));
}
__device__ __forceinline__ void mma_bf16(float* d, const unsigned* a, const unsigned* b) {
    asm volatile(
        "mma.sync.aligned.m16n8k16.row.col.f32.bf16.bf16.f32 "
        "{%0,%1,%2,%3}, {%4,%5,%6,%7}, {%8,%9}, {%0,%1,%2,%3};\n"
        : "+f"(d[0]), "+f"(d[1]), "+f"(d[2]), "+f"(d[3])
        : "r"(a[0]), "r"(a[1]), "r"(a[2]), "r"(a[3]), "r"(b[0]), "r"(b[1]));
}
__device__ __forceinline__ unsigned short bfu(__nv_bfloat16 v) {
    return *(unsigned short*)&v;
}
__device__ __forceinline__ void packsplit(float x, float y, unsigned& h, unsigned& l) {
    __nv_bfloat16 xh = __float2bfloat16(x), yh = __float2bfloat16(y);
    __nv_bfloat16 xl = __float2bfloat16(x - __bfloat162float(xh));
    __nv_bfloat16 yl = __float2bfloat16(y - __bfloat162float(yh));
    h = (unsigned)bfu(xh) | ((unsigned)bfu(yh) << 16);
    l = (unsigned)bfu(xl) | ((unsigned)bfu(yl) << 16);
}
// split 8 contiguous fp32 -> 16B hi + 16B lo
__device__ __forceinline__ void split8(const float* f, uint4& hv, uint4& lv) {
    unsigned hw[4], lw[4];
#pragma unroll
    for (int j = 0; j < 4; j++) packsplit(f[2 * j], f[2 * j + 1], hw[j], lw[j]);
    hv = make_uint4(hw[0], hw[1], hw[2], hw[3]);
    lv = make_uint4(lw[0], lw[1], lw[2], lw[3]);
}

// ======================= fp32 -> bf16 hi/lo split =======================
__global__ void conv_split(const float* __restrict__ in,
                           __nv_bfloat16* __restrict__ hi,
                           __nv_bfloat16* __restrict__ lo, int n) {
    int i = (blockIdx.x * blockDim.x + threadIdx.x) * 4;
    if (i >= n) return;
    float4 v = *(const float4*)(in + i);
    __nv_bfloat16 h[4], l[4];
    h[0] = __float2bfloat16(v.x); l[0] = __float2bfloat16(v.x - __bfloat162float(h[0]));
    h[1] = __float2bfloat16(v.y); l[1] = __float2bfloat16(v.y - __bfloat162float(h[1]));
    h[2] = __float2bfloat16(v.z); l[2] = __float2bfloat16(v.z - __bfloat162float(h[2]));
    h[3] = __float2bfloat16(v.w); l[3] = __float2bfloat16(v.w - __bfloat162float(h[3]));
    *(ushort4*)(hi + i) = *(ushort4*)h;
    *(ushort4*)(lo + i) = *(ushort4*)l;
}

// ======================= bgemm2: ldmatrix + cp.async double buffer =======================
// C[M,N] = A @ B via Ah*Bh + Ah*Bl + Al*Bh. M=2048, K mult 32, N mult 8.
// per-stage smem (32KB): Ah[128x32] +0, Al +8192, Bh[32x128] +16384, Bl +24576.
// A swizzle: off(r,s)=r*64+((s^((r>>1)&3))<<4) ; B swizzle: off(r,s)=r*256+((s^(r&7))<<4)
#define BG_STAGE 32768

__global__ __launch_bounds__(256, 2) void bgemm2(const __nv_bfloat16* __restrict__ Ahg,
                                                 const __nv_bfloat16* __restrict__ Alg,
                                                 const __nv_bfloat16* __restrict__ Bhg,
                                                 const __nv_bfloat16* __restrict__ Blg,
                                                 float* __restrict__ C,
                                                 int N, int K) {
    extern __shared__ char smem[];
    const uint32_t sb = s2u(smem);
    const int tid = threadIdx.x;
    const int lane = tid & 31, warp = tid >> 5;
    const int wm = warp >> 2, wn = warp & 3;
    const int g = lane >> 2, t = lane & 3;
    const int bm = blockIdx.y * 128, bn = blockIdx.x * 128;

    float acc[4][4][4];
#pragma unroll
    for (int mt = 0; mt < 4; mt++)
#pragma unroll
        for (int nt = 0; nt < 4; nt++)
#pragma unroll
            for (int k = 0; k < 4; k++) acc[mt][nt][k] = 0.f;

    const int nsteps = K >> 5;

    auto load_stage = [&](int st, int k0) {
        uint32_t base = sb + st * BG_STAGE;
#pragma unroll
        for (int p = 0; p < 2; p++) {
            int id = tid + p * 256;
            int r = id >> 2, sg = id & 3;
            uint32_t dst = base + r * 64 + (((sg ^ ((r >> 1) & 3))) << 4);
            size_t go = (size_t)(bm + r) * K + k0 + sg * 8;
            cpa(dst, Ahg + go);
            cpa(dst + 8192, Alg + go);
        }
#pragma unroll
        for (int p = 0; p < 2; p++) {
            int id = tid + p * 256;
            int r = id >> 4, sg = id & 15;
            uint32_t dst = base + 16384 + r * 256 + ((sg ^ (r & 7)) << 4);
            size_t go = (size_t)(k0 + r) * N + bn + sg * 8;
            cpa(dst, Bhg + go);
            cpa(dst + 8192, Blg + go);
        }
        CP_COMMIT;
    };

    load_stage(0, 0);

    for (int s = 0; s < nsteps; s++) {
        int cur = s & 1;
        if (s + 1 < nsteps) {
            load_stage(cur ^ 1, (s + 1) * 32);
            CP_WAIT1;
        } else {
            CP_WAIT0;
        }
        __syncthreads();

        uint32_t ab = sb + cur * BG_STAGE;
        uint32_t bb = ab + 16384;
        const int lr = (lane & 7) + 8 * ((lane >> 3) & 1);

#pragma unroll
        for (int kk = 0; kk < 32; kk += 16) {
            unsigned ah[4][4], al[4][4], bh[4][2], bl[4][2];
            int sgA = (kk >> 3) + (lane >> 4);
#pragma unroll
            for (int mt = 0; mt < 4; mt++) {
                int row = wm * 64 + mt * 16 + lr;
                uint32_t a = ab + row * 64 + ((sgA ^ ((row >> 1) & 3)) << 4);
                ldsm4(a, ah[mt]);
                ldsm4(a + 8192, al[mt]);
            }
            int rB = kk + lr;
#pragma unroll
            for (int nt = 0; nt < 4; nt++) {
                int sgB = wn * 4 + nt;
                uint32_t b = bb + rB * 256 + ((sgB ^ (rB & 7)) << 4);
                ldsm2t(b, bh[nt]);
                ldsm2t(b + 8192, bl[nt]);
            }
#pragma unroll
            for (int mt = 0; mt < 4; mt++)
#pragma unroll
                for (int nt = 0; nt < 4; nt++) {
                    mma_bf16(acc[mt][nt], ah[mt], bh[nt]);
                    mma_bf16(acc[mt][nt], ah[mt], bl[nt]);
                    mma_bf16(acc[mt][nt], al[mt], bh[nt]);
                }
        }
        __syncthreads();
    }

#pragma unroll
    for (int mt = 0; mt < 4; mt++) {
        int row = bm + wm * 64 + mt * 16 + g;
#pragma unroll
        for (int nt = 0; nt < 4; nt++) {
            int col = bn + wn * 32 + nt * 8 + 2 * t;
            if (col < N) {
                *(float2*)&C[(size_t)row * N + col] =
                    make_float2(acc[mt][nt][0], acc[mt][nt][1]);
                *(float2*)&C[(size_t)(row + 8) * N + col] =
                    make_float2(acc[mt][nt][2], acc[mt][nt][3]);
            }
        }
    }
}

// ======================= RMSNorm =======================
__global__ void rmsnorm_kernel(const float* __restrict__ in,
                               const float* __restrict__ w,
                               float* __restrict__ out,
                               int D, int in_stride, int out_stride) {
    const int row = blockIdx.x;
    const float* x = in + (size_t)row * in_stride;
    float* y = out + (size_t)row * out_stride;
    float ss = 0.f;
    for (int i = threadIdx.x; i < D; i += blockDim.x) { float v = x[i]; ss += v * v; }
#pragma unroll
    for (int m = 16; m; m >>= 1) ss += __shfl_xor_sync(0xffffffffu, ss, m);
    __shared__ float wsum[8];
    if ((threadIdx.x & 31) == 0) wsum[threadIdx.x >> 5] = ss;
    __syncthreads();
    float tot = 0.f;
#pragma unroll
    for (int i = 0; i < 8; i++) tot += wsum[i];
    float scale = rsqrtf(tot / (float)D + 1e-6f);
    for (int i = threadIdx.x; i < D; i += blockDim.x) y[i] = x[i] * scale * w[i];
}

// ======================= RoPE =======================
#define LOG2_10000_OVER_32 0.4152410118609203f

__global__ void rope_q_kernel(float* __restrict__ q) {
    int w = (blockIdx.x * blockDim.x + threadIdx.x) >> 5;
    int lane = threadIdx.x & 31;
    if (w >= SQ * HH) return;
    int s = w >> 4, h = w & 15;
    float* base = q + (size_t)s * (HH * DQQ) + h * DQQ + DNN;
    float x0 = base[2 * lane];
    float x1 = base[2 * lane + 1];
    float invf = exp2f(-(float)lane * LOG2_10000_OVER_32);
    float ang = (float)s * invf;
    float sn, cs;
    sincosf(ang, &sn, &cs);
    float o0 = x0 * cs - x1 * sn;
    float o1 = x1 * cs + x0 * sn;
    __syncwarp();
    base[lane] = o0;
    base[32 + lane] = o1;
}

__global__ void rope_k_kernel(const float* __restrict__ ckv, float* __restrict__ kpe) {
    int w = (blockIdx.x * blockDim.x + threadIdx.x) >> 5;
    int lane = threadIdx.x & 31;
    if (w >= SQ) return;
    const float* base = ckv + (size_t)w * (KLR + DRR) + KLR;
    float x0 = base[2 * lane];
    float x1 = base[2 * lane + 1];
    float invf = exp2f(-(float)lane * LOG2_10000_OVER_32);
    float ang = (float)w * invf;
    float sn, cs;
    sincosf(ang, &sn, &cs);
    kpe[(size_t)w * DRR + lane]      = x0 * cs - x1 * sn;
    kpe[(size_t)w * DRR + 32 + lane] = x1 * cs + x0 * sn;
}

// ======================= flash2: tensor-core flash attention =======================
// BM=128 (8 warps x 16 rows), BN=64, D=192, DV=128, bf16x3 everywhere.
// smem: Qh 0 (49152), Ql 49152, Kh 98304 (24576), Kl 122880, Vh 147456 (16384), Vl 163840
#define FL2_SMEM 180224
#define OQH 0
#define OQL 49152
#define OKH 98304
#define OKL 122880
#define OVH 147456
#define OVL 163840

__global__ __launch_bounds__(256, 1) void flash2(const float* __restrict__ q,
                                                 const float* __restrict__ kv,
                                                 const float* __restrict__ kpe,
                                                 float* __restrict__ o) {
    extern __shared__ char smem[];
    const uint32_t sb = s2u(smem);
    const int tid = threadIdx.x, lane = tid & 31, warp = tid >> 5;
    const int g = lane >> 2, t = lane & 3;
    const int h = blockIdx.y;
    const int qb = gridDim.x - 1 - blockIdx.x;   // reverse for causal balance
    const int q0 = qb * 128;
    const int r0 = warp * 16;
    const float scale = 0.07216878364870322f;    // 1/sqrt(192)

    // ---- load Q tile (fp32 -> bf16 hi/lo, swizzled k-major [128][192]) ----
    for (int i = tid; i < 128 * 24; i += 256) {
        int r = i / 24, sg = i % 24;
        const float4* src = (const float4*)(q + (size_t)(q0 + r) * (HH * DQQ) + h * DQQ + sg * 8);
        float f[8];
        *(float4*)&f[0] = src[0];
        *(float4*)&f[4] = src[1];
        uint4 hv, lv;
        split8(f, hv, lv);
        uint32_t off = r * 384 + ((sg ^ (r & 7)) << 4);
        *(uint4*)(smem + OQH + off) = hv;
        *(uint4*)(smem + OQL + off) = lv;
    }

    float m0 = -1e30f, m1 = -1e30f, l0 = 0.f, l1 = 0.f;
    float oacc[16][4];
#pragma unroll
    for (int nv = 0; nv < 16; nv++)
#pragma unroll
        for (int k = 0; k < 4; k++) oacc[nv][k] = 0.f;

    const int nkb = 2 * qb + 2;
    for (int kb = 0; kb < nkb; kb++) {
        const int k0 = kb * 64;
        __syncthreads();
        // ---- load K tile [64][192] ----
        for (int i = tid; i < 64 * 24; i += 256) {
            int r = i / 24, sg = i % 24;
            float f[8];
            if (sg < 16) {
                const float4* src = (const float4*)(kv + (size_t)(k0 + r) * (HH * 256) + h * 256 + sg * 8);
                *(float4*)&f[0] = src[0];
                *(float4*)&f[4] = src[1];
            } else {
                const float4* src = (const float4*)(kpe + (size_t)(k0 + r) * DRR + (sg - 16) * 8);
                *(float4*)&f[0] = src[0];
                *(float4*)&f[4] = src[1];
            }
            uint4 hv, lv;
            split8(f, hv, lv);
            uint32_t off = r * 384 + ((sg ^ (r & 7)) << 4);
            *(uint4*)(smem + OKH + off) = hv;
            *(uint4*)(smem + OKL + off) = lv;
        }
        // ---- load V tile [64][128] ----
        for (int i = tid; i < 64 * 16; i += 256) {
            int r = i / 16, sg = i % 16;
            const float4* src = (const float4*)(kv + (size_t)(k0 + r) * (HH * 256) + h * 256 + DNN + sg * 8);
            float f[8];
            *(float4*)&f[0] = src[0];
            *(float4*)&f[4] = src[1];
            uint4 hv, lv;
            split8(f, hv, lv);
            uint32_t off = r * 256 + ((sg ^ (r & 7)) << 4);
            *(uint4*)(smem + OVH + off) = hv;
            *(uint4*)(smem + OVL + off) = lv;
        }
        __syncthreads();

        // ---- S = Q @ K^T ----
        float sacc[8][4];
#pragma unroll
        for (int nt = 0; nt < 8; nt++)
#pragma unroll
            for (int k = 0; k < 4; k++) sacc[nt][k] = 0.f;

        const int lr = (lane & 7) + 8 * ((lane >> 3) & 1);
#pragma unroll
        for (int kk = 0; kk < 192; kk += 16) {
            unsigned ah[4], al[4];
            int rowA = r0 + lr;
            int sgA = (kk >> 3) + (lane >> 4);
            uint32_t a = sb + OQH + rowA * 384 + ((sgA ^ (rowA & 7)) << 4);
            ldsm4(a, ah);
            ldsm4(a + (OQL - OQH), al);
            int sgB = (kk >> 3) + ((lane >> 3) & 1);
#pragma unroll
            for (int nt = 0; nt < 8; nt++) {
                unsigned bh[2], bl[2];
                int rB = nt * 8 + (lane & 7);
                uint32_t b = sb + OKH + rB * 384 + ((sgB ^ (rB & 7)) << 4);
                ldsm2(b, bh);
                ldsm2(b + (OKL - OKH), bl);
                mma_bf16(sacc[nt], ah, bh);
                mma_bf16(sacc[nt], ah, bl);
                mma_bf16(sacc[nt], al, bh);
            }
        }

        // ---- mask + online softmax ----
        const int qi0 = q0 + r0 + g;
        const int qi1 = qi0 + 8;
        const bool full = (k0 + 63 <= q0 + r0);
        float mx0 = -1e30f, mx1 = -1e30f;
#pragma unroll
        for (int nt = 0; nt < 8; nt++) {
            int c = k0 + nt * 8 + 2 * t;
            float s00 = sacc[nt][0] * scale, s01 = sacc[nt][1] * scale;
            float s10 = sacc[nt][2] * scale, s11 = sacc[nt][3] * scale;
            if (!full) {
                if (c > qi0)     s00 = -1e30f;
                if (c + 1 > qi0) s01 = -1e30f;
                if (c > qi1)     s10 = -1e30f;
                if (c + 1 > qi1) s11 = -1e30f;
            }
            sacc[nt][0] = s00; sacc[nt][1] = s01;
            sacc[nt][2] = s10; sacc[nt][3] = s11;
            mx0 = fmaxf(mx0, fmaxf(s00, s01));
            mx1 = fmaxf(mx1, fmaxf(s10, s11));
        }
        mx0 = fmaxf(mx0, __shfl_xor_sync(0xffffffffu, mx0, 1));
        mx0 = fmaxf(mx0, __shfl_xor_sync(0xffffffffu, mx0, 2));
        mx1 = fmaxf(mx1, __shfl_xor_sync(0xffffffffu, mx1, 1));
        mx1 = fmaxf(mx1, __shfl_xor_sync(0xffffffffu, mx1, 2));

        float mn0 = fmaxf(m0, mx0), mn1 = fmaxf(m1, mx1);
        float a0 = __expf(m0 - mn0), a1 = __expf(m1 - mn1);
        float s0 = 0.f, s1 = 0.f;
#pragma unroll
        for (int nt = 0; nt < 8; nt++) {
            float p00 = __expf(sacc[nt][0] - mn0);
            float p01 = __expf(sacc[nt][1] - mn0);
            float p10 = __expf(sacc[nt][2] - mn1);
            float p11 = __expf(sacc[nt][3] - mn1);
            sacc[nt][0] = p00; sacc[nt][1] = p01;
            sacc[nt][2] = p10; sacc[nt][3] = p11;
            s0 += p00 + p01;
            s1 += p10 + p11;
        }
        s0 += __shfl_xor_sync(0xffffffffu, s0, 1);
        s0 += __shfl_xor_sync(0xffffffffu, s0, 2);
        s1 += __shfl_xor_sync(0xffffffffu, s1, 1);
        s1 += __shfl_xor_sync(0xffffffffu, s1, 2);
        l0 = l0 * a0 + s0;
        l1 = l1 * a1 + s1;
        m0 = mn0; m1 = mn1;
#pragma unroll
        for (int nv = 0; nv < 16; nv++) {
            oacc[nv][0] *= a0; oacc[nv][1] *= a0;
            oacc[nv][2] *= a1; oacc[nv][3] *= a1;
        }

        // ---- O += P @ V ----
#pragma unroll
        for (int u = 0; u < 4; u++) {
            unsigned pah[4], pal[4];
            packsplit(sacc[2 * u][0],     sacc[2 * u][1],     pah[0], pal[0]);
            packsplit(sacc[2 * u][2],     sacc[2 * u][3],     pah[1], pal[1]);
            packsplit(sacc[2 * u + 1][0], sacc[2 * u + 1][1], pah[2], pal[2]);
            packsplit(sacc[2 * u + 1][2], sacc[2 * u + 1][3], pah[3], pal[3]);
            int rV = u * 16 + lr;
#pragma unroll
            for (int nv = 0; nv < 16; nv++) {
                unsigned bvh[2], bvl[2];
                uint32_t a = sb + OVH + rV * 256 + ((nv ^ (rV & 7)) << 4);
                ldsm2t(a, bvh);
                ldsm2t(a + (OVL - OVH), bvl);
                mma_bf16(oacc[nv], pah, bvh);
                mma_bf16(oacc[nv], pah, bvl);
                mma_bf16(oacc[nv], pal, bvh);
            }
        }
    }

    // ---- epilogue ----
    float i0 = 1.f / l0, i1 = 1.f / l1;
    int row0 = q0 + r0 + g;
#pragma unroll
    for (int nv = 0; nv < 16; nv++) {
        int col = h * DVV + nv * 8 + 2 * t;
        *(float2*)&o[(size_t)row0 * (HH * DVV) + col] =
            make_float2(oacc[nv][0] * i0, oacc[nv][1] * i0);
        *(float2*)&o[(size_t)(row0 + 8) * (HH * DVV) + col] =
            make_float2(oacc[nv][2] * i1, oacc[nv][3] * i1);
    }
}

// ======================= launch =======================
extern "C" void kernel_launch(void* const* d_in, const int* in_sizes, int n_in,
                              void* d_out, int out_size) {
    const float* x       = (const float*)d_in[0];
    const float* w_q_a   = (const float*)d_in[1];
    const float* q_a_ln  = (const float*)d_in[2];
    const float* w_q_b   = (const float*)d_in[3];
    const float* w_kv_a  = (const float*)d_in[4];
    const float* kv_a_ln = (const float*)d_in[5];
    const float* w_kv_b  = (const float*)d_in[6];
    const float* w_out   = (const float*)d_in[7];
    float* out = (float*)d_out;

    float *qa, *qbuf, *ckv, *ckvn, *kvb, *kpe, *obuf;
    __nv_bfloat16 *Ah, *Al, *Bh, *Bl;
    cudaGetSymbolAddress((void**)&qa,   g_qa);
    cudaGetSymbolAddress((void**)&qbuf, g_q);
    cudaGetSymbolAddress((void**)&ckv,  g_ckv);
    cudaGetSymbolAddress((void**)&ckvn, g_ckvn);
    cudaGetSymbolAddress((void**)&kvb,  g_kv);
    cudaGetSymbolAddress((void**)&kpe,  g_kpe);
    cudaGetSymbolAddress((void**)&obuf, g_o);
    cudaGetSymbolAddress((void**)&Ah,   g_Ah);
    cudaGetSymbolAddress((void**)&Al,   g_Al);
    cudaGetSymbolAddress((void**)&Bh,   g_Bh);
    cudaGetSymbolAddress((void**)&Bl,   g_Bl);

    cudaFuncSetAttribute(bgemm2, cudaFuncAttributeMaxDynamicSharedMemorySize, 2 * BG_STAGE);
    cudaFuncSetAttribute(flash2, cudaFuncAttributeMaxDynamicSharedMemorySize, FL2_SMEM);

    dim3 blk(256);
    auto conv = [&](const float* src, __nv_bfloat16* h, __nv_bfloat16* l, int n) {
        conv_split<<<(n / 4 + 255) / 256, blk>>>(src, h, l, n);
    };
    auto gemm = [&](const __nv_bfloat16* ah, const __nv_bfloat16* al,
                    const __nv_bfloat16* bh, const __nv_bfloat16* bl,
                    float* c, int N, int K) {
        bgemm2<<<dim3((N + 127) / 128, SQ / 128), blk, 2 * BG_STAGE>>>(ah, al, bh, bl, c, N, K);
    };

    conv(x, Ah, Al, SQ * EE);

    conv(w_q_a, Bh, Bl, EE * QLR);
    gemm(Ah, Al, Bh, Bl, qa, QLR, EE);

    conv(w_kv_a, Bh, Bl, EE * (KLR + DRR));
    gemm(Ah, Al, Bh, Bl, ckv, KLR + DRR, EE);

    rmsnorm_kernel<<<SQ, blk>>>(qa, q_a_ln, qa, QLR, QLR, QLR);
    rmsnorm_kernel<<<SQ, blk>>>(ckv, kv_a_ln, ckvn, KLR, KLR + DRR, KLR);

    conv(qa, Ah, Al, SQ * QLR);
    conv(w_q_b, Bh, Bl, QLR * HH * DQQ);
    gemm(Ah, Al, Bh, Bl, qbuf, HH * DQQ, QLR);

    conv(ckvn, Ah, Al, SQ * KLR);
    conv(w_kv_b, Bh, Bl, KLR * HH * 256);
    gemm(Ah, Al, Bh, Bl, kvb, HH * 256, KLR);

    rope_q_kernel<<<(SQ * HH * 32) / 256, blk>>>(qbuf);
    rope_k_kernel<<<(SQ * 32 + 255) / 256, blk>>>(ckv, kpe);

    flash2<<<dim3(SQ / 128, HH), blk, FL2_SMEM>>>(qbuf, kvb, kpe, obuf);

    conv(obuf, Ah, Al, SQ * HH * DVV);
    conv(w_out, Bh, Bl, HH * DVV * EE);
    gemm(Ah, Al, Bh, Bl, out, EE, EE);
}

// round 6
// speedup vs baseline: 4.4059x; 1.1626x over previous
#include <cuda_runtime.h>
#include <cuda_bf16.h>
#include <math.h>
#include <stdint.h>

#define SQ   2048
#define EE   2048
#define HH   16
#define QLR  1536
#define KLR  512
#define DNN  128
#define DRR  64
#define DVV  128
#define DQQ  192

// -------- scratch --------
__device__ float g_qa  [SQ * QLR];
__device__ float g_q   [SQ * HH * DQQ];
__device__ float g_ckv [SQ * (KLR + DRR)];

__device__ __nv_bfloat16 g_Ah [SQ * EE];
__device__ __nv_bfloat16 g_Al [SQ * EE];
__device__ __nv_bfloat16 g_Bh [QLR * 3072];
__device__ __nv_bfloat16 g_Bl [QLR * 3072];
__device__ __nv_bfloat16 g_kvh[SQ * HH * 256];
__device__ __nv_bfloat16 g_kvl[SQ * HH * 256];
__device__ __nv_bfloat16 g_kpeh[SQ * DRR];
__device__ __nv_bfloat16 g_kpel[SQ * DRR];

// ======================= helpers =======================
__device__ __forceinline__ uint32_t s2u(const void* p) {
    return (uint32_t)__cvta_generic_to_shared(p);
}
__device__ __forceinline__ void cpa(uint32_t d, const void* s) {
    asm volatile("cp.async.cg.shared.global [%0], [%1], 16;\n" :: "r"(d), "l"(s));
}
#define CP_COMMIT asm volatile("cp.async.commit_group;\n")
#define CP_WAIT0  asm volatile("cp.async.wait_group 0;\n")
#define CP_WAIT1  asm volatile("cp.async.wait_group 1;\n")
#define CP_WAIT2  asm volatile("cp.async.wait_group 2;\n")

__device__ __forceinline__ void ldsm4(uint32_t a, unsigned* d) {
    asm volatile("ldmatrix.sync.aligned.m8n8.x4.shared.b16 {%0,%1,%2,%3}, [%4];\n"
        : "=r"(d[0]), "=r"(d[1]), "=r"(d[2]), "=r"(d[3]) : "r"(a));
}
__device__ __forceinline__ void ldsm2(uint32_t a, unsigned* d) {
    asm volatile("ldmatrix.sync.aligned.m8n8.x2.shared.b16 {%0,%1}, [%2];\n"
        : "=r"(d[0]), "=r"(d[1]) : "r"(a));
}
__device__ __forceinline__ void ldsm2t(uint32_t a, unsigned* d) {
    asm volatile("ldmatrix.sync.aligned.m8n8.x2.trans.shared.b16 {%0,%1}, [%2];\n"
        : "=r"(d[0]), "=r"(d[1]) : "r"(a));
}
__device__ __forceinline__ void mma_bf16(float* d, const unsigned* a, const unsigned* b) {
    asm volatile(
        "mma.sync.aligned.m16n8k16.row.col.f32.bf16.bf16.f32 "
        "{%0,%1,%2,%3}, {%4,%5,%6,%7}, {%8,%9}, {%0,%1,%2,%3};\n"
        : "+f"(d[0]), "+f"(d[1]), "+f"(d[2]), "+f"(d[3])
        : "r"(a[0]), "r"(a[1]), "r"(a[2]), "r"(a[3]), "r"(b[0]), "r"(b[1]));
}
__device__ __forceinline__ unsigned short bfu(__nv_bfloat16 v) {
    return *(unsigned short*)&v;
}
__device__ __forceinline__ void packsplit(float x, float y, unsigned& h, unsigned& l) {
    __nv_bfloat16 xh = __float2bfloat16(x), yh = __float2bfloat16(y);
    __nv_bfloat16 xl = __float2bfloat16(x - __bfloat162float(xh));
    __nv_bfloat16 yl = __float2bfloat16(y - __bfloat162float(yh));
    h = (unsigned)bfu(xh) | ((unsigned)bfu(yh) << 16);
    l = (unsigned)bfu(xl) | ((unsigned)bfu(yl) << 16);
}
__device__ __forceinline__ void split8(const float* f, uint4& hv, uint4& lv) {
    unsigned hw[4], lw[4];
#pragma unroll
    for (int j = 0; j < 4; j++) packsplit(f[2 * j], f[2 * j + 1], hw[j], lw[j]);
    hv = make_uint4(hw[0], hw[1], hw[2], hw[3]);
    lv = make_uint4(lw[0], lw[1], lw[2], lw[3]);
}

// ======================= fp32 -> bf16 hi/lo split (8 elts/thread) ===========
__global__ void conv_split(const float* __restrict__ in,
                           __nv_bfloat16* __restrict__ hi,
                           __nv_bfloat16* __restrict__ lo, int n) {
    int i = (blockIdx.x * blockDim.x + threadIdx.x) * 8;
    if (i >= n) return;
    float f[8];
    *(float4*)&f[0] = *(const float4*)(in + i);
    *(float4*)&f[4] = *(const float4*)(in + i + 4);
    uint4 hv, lv;
    split8(f, hv, lv);
    *(uint4*)(hi + i) = hv;
    *(uint4*)(lo + i) = lv;
}

// ======================= RMSNorm fused with split ===========================
__global__ void rmsnorm_split(const float* __restrict__ in,
                              const float* __restrict__ w,
                              __nv_bfloat16* __restrict__ hi,
                              __nv_bfloat16* __restrict__ lo,
                              int D, int in_stride) {
    const int row = blockIdx.x;
    const float* x = in + (size_t)row * in_stride;
    float ss = 0.f;
    for (int i = threadIdx.x; i < D; i += blockDim.x) { float v = x[i]; ss += v * v; }
#pragma unroll
    for (int m = 16; m; m >>= 1) ss += __shfl_xor_sync(0xffffffffu, ss, m);
    __shared__ float wsum[8];
    if ((threadIdx.x & 31) == 0) wsum[threadIdx.x >> 5] = ss;
    __syncthreads();
    float tot = 0.f;
#pragma unroll
    for (int i = 0; i < 8; i++) tot += wsum[i];
    float scale = rsqrtf(tot / (float)D + 1e-6f);
    for (int i = threadIdx.x; i < D; i += blockDim.x) {
        float v = x[i] * scale * w[i];
        __nv_bfloat16 h = __float2bfloat16(v);
        __nv_bfloat16 l = __float2bfloat16(v - __bfloat162float(h));
        hi[(size_t)row * D + i] = h;
        lo[(size_t)row * D + i] = l;
    }
}

// ======================= bgemm2: 3-stage cp.async + ldmatrix ================
// C = A @ B via Ah*Bh + Ah*Bl + Al*Bh. M=2048, K mult 32, N mult 8.
// stage (32KB): Ah[128x32] +0, Al +8192, Bh[32x128] +16384, Bl +24576
#define BG_STAGE 32768
#define BG_SMEM  (3 * BG_STAGE)

__global__ __launch_bounds__(256, 2) void bgemm2(const __nv_bfloat16* __restrict__ Ahg,
                                                 const __nv_bfloat16* __restrict__ Alg,
                                                 const __nv_bfloat16* __restrict__ Bhg,
                                                 const __nv_bfloat16* __restrict__ Blg,
                                                 float* __restrict__ C,
                                                 __nv_bfloat16* __restrict__ Ch,
                                                 __nv_bfloat16* __restrict__ Cl,
                                                 int N, int K, int mode) {
    extern __shared__ char smem[];
    const uint32_t sb = s2u(smem);
    const int tid = threadIdx.x;
    const int lane = tid & 31, warp = tid >> 5;
    const int wm = warp >> 2, wn = warp & 3;
    const int g = lane >> 2, t = lane & 3;
    const int bm = blockIdx.y * 128, bn = blockIdx.x * 128;

    float acc[4][4][4];
#pragma unroll
    for (int mt = 0; mt < 4; mt++)
#pragma unroll
        for (int nt = 0; nt < 4; nt++)
#pragma unroll
            for (int k = 0; k < 4; k++) acc[mt][nt][k] = 0.f;

    const int nsteps = K >> 5;

    auto load_stage = [&](int s) {
        uint32_t base = sb + (s % 3) * BG_STAGE;
        int k0 = s << 5;
#pragma unroll
        for (int p = 0; p < 2; p++) {
            int id = tid + p * 256;
            int r = id >> 2, sg = id & 3;
            uint32_t dst = base + r * 64 + (((sg ^ ((r >> 1) & 3))) << 4);
            size_t go = (size_t)(bm + r) * K + k0 + sg * 8;
            cpa(dst, Ahg + go);
            cpa(dst + 8192, Alg + go);
        }
#pragma unroll
        for (int p = 0; p < 2; p++) {
            int id = tid + p * 256;
            int r = id >> 4, sg = id & 15;
            uint32_t dst = base + 16384 + r * 256 + ((sg ^ (r & 7)) << 4);
            size_t go = (size_t)(k0 + r) * N + bn + sg * 8;
            cpa(dst, Bhg + go);
            cpa(dst + 8192, Blg + go);
        }
        CP_COMMIT;
    };

    load_stage(0);
    if (nsteps > 1) load_stage(1);

    for (int s = 0; s < nsteps; s++) {
        if (s + 2 < nsteps) {
            load_stage(s + 2);
            CP_WAIT2;
        } else if (s + 1 < nsteps) {
            CP_WAIT1;
        } else {
            CP_WAIT0;
        }
        __syncthreads();

        uint32_t ab = sb + (s % 3) * BG_STAGE;
        uint32_t bb = ab + 16384;
        const int lr = (lane & 7) + 8 * ((lane >> 3) & 1);

#pragma unroll
        for (int kk = 0; kk < 32; kk += 16) {
            unsigned ah[4][4], al[4][4], bh[4][2], bl[4][2];
            int sgA = (kk >> 3) + (lane >> 4);
#pragma unroll
            for (int mt = 0; mt < 4; mt++) {
                int row = wm * 64 + mt * 16 + lr;
                uint32_t a = ab + row * 64 + ((sgA ^ ((row >> 1) & 3)) << 4);
                ldsm4(a, ah[mt]);
                ldsm4(a + 8192, al[mt]);
            }
            int rB = kk + lr;
#pragma unroll
            for (int nt = 0; nt < 4; nt++) {
                int sgB = wn * 4 + nt;
                uint32_t b = bb + rB * 256 + ((sgB ^ (rB & 7)) << 4);
                ldsm2t(b, bh[nt]);
                ldsm2t(b + 8192, bl[nt]);
            }
#pragma unroll
            for (int mt = 0; mt < 4; mt++)
#pragma unroll
                for (int nt = 0; nt < 4; nt++) {
                    mma_bf16(acc[mt][nt], ah[mt], bh[nt]);
                    mma_bf16(acc[mt][nt], ah[mt], bl[nt]);
                    mma_bf16(acc[mt][nt], al[mt], bh[nt]);
                }
        }
        __syncthreads();
    }

    if (mode == 0) {
#pragma unroll
        for (int mt = 0; mt < 4; mt++) {
            int row = bm + wm * 64 + mt * 16 + g;
#pragma unroll
            for (int nt = 0; nt < 4; nt++) {
                int col = bn + wn * 32 + nt * 8 + 2 * t;
                if (col < N) {
                    *(float2*)&C[(size_t)row * N + col] =
                        make_float2(acc[mt][nt][0], acc[mt][nt][1]);
                    *(float2*)&C[(size_t)(row + 8) * N + col] =
                        make_float2(acc[mt][nt][2], acc[mt][nt][3]);
                }
            }
        }
    } else {
        // split epilogue: write bf16 hi/lo pair buffers
#pragma unroll
        for (int mt = 0; mt < 4; mt++) {
            int row = bm + wm * 64 + mt * 16 + g;
#pragma unroll
            for (int nt = 0; nt < 4; nt++) {
                int col = bn + wn * 32 + nt * 8 + 2 * t;
                unsigned hw, lw;
                packsplit(acc[mt][nt][0], acc[mt][nt][1], hw, lw);
                *(unsigned*)(Ch + (size_t)row * N + col) = hw;
                *(unsigned*)(Cl + (size_t)row * N + col) = lw;
                packsplit(acc[mt][nt][2], acc[mt][nt][3], hw, lw);
                *(unsigned*)(Ch + (size_t)(row + 8) * N + col) = hw;
                *(unsigned*)(Cl + (size_t)(row + 8) * N + col) = lw;
            }
        }
    }
}

// ======================= RoPE =======================
#define LOG2_10000_OVER_32 0.4152410118609203f

__global__ void rope_q_kernel(float* __restrict__ q) {
    int w = (blockIdx.x * blockDim.x + threadIdx.x) >> 5;
    int lane = threadIdx.x & 31;
    if (w >= SQ * HH) return;
    int s = w >> 4, h = w & 15;
    float* base = q + (size_t)s * (HH * DQQ) + h * DQQ + DNN;
    float x0 = base[2 * lane];
    float x1 = base[2 * lane + 1];
    float invf = exp2f(-(float)lane * LOG2_10000_OVER_32);
    float ang = (float)s * invf;
    float sn, cs;
    sincosf(ang, &sn, &cs);
    float o0 = x0 * cs - x1 * sn;
    float o1 = x1 * cs + x0 * sn;
    __syncwarp();
    base[lane] = o0;
    base[32 + lane] = o1;
}

__global__ void rope_k_split(const float* __restrict__ ckv,
                             __nv_bfloat16* __restrict__ kpeh,
                             __nv_bfloat16* __restrict__ kpel) {
    int w = (blockIdx.x * blockDim.x + threadIdx.x) >> 5;
    int lane = threadIdx.x & 31;
    if (w >= SQ) return;
    const float* base = ckv + (size_t)w * (KLR + DRR) + KLR;
    float x0 = base[2 * lane];
    float x1 = base[2 * lane + 1];
    float invf = exp2f(-(float)lane * LOG2_10000_OVER_32);
    float ang = (float)w * invf;
    float sn, cs;
    sincosf(ang, &sn, &cs);
    float o0 = x0 * cs - x1 * sn;
    float o1 = x1 * cs + x0 * sn;
    __nv_bfloat16 h0 = __float2bfloat16(o0);
    __nv_bfloat16 h1 = __float2bfloat16(o1);
    kpeh[(size_t)w * DRR + lane]      = h0;
    kpeh[(size_t)w * DRR + 32 + lane] = h1;
    kpel[(size_t)w * DRR + lane]      = __float2bfloat16(o0 - __bfloat162float(h0));
    kpel[(size_t)w * DRR + 32 + lane] = __float2bfloat16(o1 - __bfloat162float(h1));
}

// ======================= flash2: tensor-core flash attention ================
// BM=128 (8 warps x 16 rows), BN=64. K/V arrive pre-split bf16 -> cp.async.
#define FL2_SMEM 180224
#define OQH 0
#define OQL 49152
#define OKH 98304
#define OKL 122880
#define OVH 147456
#define OVL 163840

__global__ __launch_bounds__(256, 1) void flash2(const float* __restrict__ q,
                                                 const __nv_bfloat16* __restrict__ kvh,
                                                 const __nv_bfloat16* __restrict__ kvl,
                                                 const __nv_bfloat16* __restrict__ kpeh,
                                                 const __nv_bfloat16* __restrict__ kpel,
                                                 __nv_bfloat16* __restrict__ Oh,
                                                 __nv_bfloat16* __restrict__ Ol) {
    extern __shared__ char smem[];
    const uint32_t sb = s2u(smem);
    const int tid = threadIdx.x, lane = tid & 31, warp = tid >> 5;
    const int g = lane >> 2, t = lane & 3;
    const int h = blockIdx.y;
    const int qb = gridDim.x - 1 - blockIdx.x;
    const int q0 = qb * 128;
    const int r0 = warp * 16;
    const float scale = 0.07216878364870322f;

    // Q tile: fp32 -> split once per block
    for (int i = tid; i < 128 * 24; i += 256) {
        int r = i / 24, sg = i % 24;
        const float4* src = (const float4*)(q + (size_t)(q0 + r) * (HH * DQQ) + h * DQQ + sg * 8);
        float f[8];
        *(float4*)&f[0] = src[0];
        *(float4*)&f[4] = src[1];
        uint4 hv, lv;
        split8(f, hv, lv);
        uint32_t off = r * 384 + ((sg ^ (r & 7)) << 4);
        *(uint4*)(smem + OQH + off) = hv;
        *(uint4*)(smem + OQL + off) = lv;
    }

    float m0 = -1e30f, m1 = -1e30f, l0 = 0.f, l1 = 0.f;
    float oacc[16][4];
#pragma unroll
    for (int nv = 0; nv < 16; nv++)
#pragma unroll
        for (int k = 0; k < 4; k++) oacc[nv][k] = 0.f;

    const int nkb = 2 * qb + 2;
    for (int kb = 0; kb < nkb; kb++) {
        const int k0 = kb * 64;
        __syncthreads();
        // K tile via cp.async (pre-split)
        for (int i = tid; i < 64 * 24; i += 256) {
            int r = i / 24, sg = i % 24;
            uint32_t off = r * 384 + ((sg ^ (r & 7)) << 4);
            if (sg < 16) {
                size_t go = (size_t)(k0 + r) * (HH * 256) + h * 256 + sg * 8;
                cpa(sb + OKH + off, kvh + go);
                cpa(sb + OKL + off, kvl + go);
            } else {
                size_t go = (size_t)(k0 + r) * DRR + (sg - 16) * 8;
                cpa(sb + OKH + off, kpeh + go);
                cpa(sb + OKL + off, kpel + go);
            }
        }
        // V tile via cp.async
        for (int i = tid; i < 64 * 16; i += 256) {
            int r = i / 16, sg = i % 16;
            uint32_t off = r * 256 + ((sg ^ (r & 7)) << 4);
            size_t go = (size_t)(k0 + r) * (HH * 256) + h * 256 + DNN + sg * 8;
            cpa(sb + OVH + off, kvh + go);
            cpa(sb + OVL + off, kvl + go);
        }
        CP_COMMIT;
        CP_WAIT0;
        __syncthreads();

        // S = Q @ K^T
        float sacc[8][4];
#pragma unroll
        for (int nt = 0; nt < 8; nt++)
#pragma unroll
            for (int k = 0; k < 4; k++) sacc[nt][k] = 0.f;

        const int lr = (lane & 7) + 8 * ((lane >> 3) & 1);
#pragma unroll
        for (int kk = 0; kk < 192; kk += 16) {
            unsigned ah[4], al[4];
            int rowA = r0 + lr;
            int sgA = (kk >> 3) + (lane >> 4);
            uint32_t a = sb + OQH + rowA * 384 + ((sgA ^ (rowA & 7)) << 4);
            ldsm4(a, ah);
            ldsm4(a + (OQL - OQH), al);
            int sgB = (kk >> 3) + ((lane >> 3) & 1);
#pragma unroll
            for (int nt = 0; nt < 8; nt++) {
                unsigned bh[2], bl[2];
                int rB = nt * 8 + (lane & 7);
                uint32_t b = sb + OKH + rB * 384 + ((sgB ^ (rB & 7)) << 4);
                ldsm2(b, bh);
                ldsm2(b + (OKL - OKH), bl);
                mma_bf16(sacc[nt], ah, bh);
                mma_bf16(sacc[nt], ah, bl);
                mma_bf16(sacc[nt], al, bh);
            }
        }

        // mask + online softmax
        const int qi0 = q0 + r0 + g;
        const int qi1 = qi0 + 8;
        const bool full = (k0 + 63 <= q0 + r0);
        float mx0 = -1e30f, mx1 = -1e30f;
#pragma unroll
        for (int nt = 0; nt < 8; nt++) {
            int c = k0 + nt * 8 + 2 * t;
            float s00 = sacc[nt][0] * scale, s01 = sacc[nt][1] * scale;
            float s10 = sacc[nt][2] * scale, s11 = sacc[nt][3] * scale;
            if (!full) {
                if (c > qi0)     s00 = -1e30f;
                if (c + 1 > qi0) s01 = -1e30f;
                if (c > qi1)     s10 = -1e30f;
                if (c + 1 > qi1) s11 = -1e30f;
            }
            sacc[nt][0] = s00; sacc[nt][1] = s01;
            sacc[nt][2] = s10; sacc[nt][3] = s11;
            mx0 = fmaxf(mx0, fmaxf(s00, s01));
            mx1 = fmaxf(mx1, fmaxf(s10, s11));
        }
        mx0 = fmaxf(mx0, __shfl_xor_sync(0xffffffffu, mx0, 1));
        mx0 = fmaxf(mx0, __shfl_xor_sync(0xffffffffu, mx0, 2));
        mx1 = fmaxf(mx1, __shfl_xor_sync(0xffffffffu, mx1, 1));
        mx1 = fmaxf(mx1, __shfl_xor_sync(0xffffffffu, mx1, 2));

        float mn0 = fmaxf(m0, mx0), mn1 = fmaxf(m1, mx1);
        float a0 = __expf(m0 - mn0), a1 = __expf(m1 - mn1);
        float s0 = 0.f, s1 = 0.f;
#pragma unroll
        for (int nt = 0; nt < 8; nt++) {
            float p00 = __expf(sacc[nt][0] - mn0);
            float p01 = __expf(sacc[nt][1] - mn0);
            float p10 = __expf(sacc[nt][2] - mn1);
            float p11 = __expf(sacc[nt][3] - mn1);
            sacc[nt][0] = p00; sacc[nt][1] = p01;
            sacc[nt][2] = p10; sacc[nt][3] = p11;
            s0 += p00 + p01;
            s1 += p10 + p11;
        }
        s0 += __shfl_xor_sync(0xffffffffu, s0, 1);
        s0 += __shfl_xor_sync(0xffffffffu, s0, 2);
        s1 += __shfl_xor_sync(0xffffffffu, s1, 1);
        s1 += __shfl_xor_sync(0xffffffffu, s1, 2);
        l0 = l0 * a0 + s0;
        l1 = l1 * a1 + s1;
        m0 = mn0; m1 = mn1;
#pragma unroll
        for (int nv = 0; nv < 16; nv++) {
            oacc[nv][0] *= a0; oacc[nv][1] *= a0;
            oacc[nv][2] *= a1; oacc[nv][3] *= a1;
        }

        // O += P @ V
#pragma unroll
        for (int u = 0; u < 4; u++) {
            unsigned pah[4], pal[4];
            packsplit(sacc[2 * u][0],     sacc[2 * u][1],     pah[0], pal[0]);
            packsplit(sacc[2 * u][2],     sacc[2 * u][3],     pah[1], pal[1]);
            packsplit(sacc[2 * u + 1][0], sacc[2 * u + 1][1], pah[2], pal[2]);
            packsplit(sacc[2 * u + 1][2], sacc[2 * u + 1][3], pah[3], pal[3]);
            int rV = u * 16 + lr;
#pragma unroll
            for (int nv = 0; nv < 16; nv++) {
                unsigned bvh[2], bvl[2];
                uint32_t a = sb + OVH + rV * 256 + ((nv ^ (rV & 7)) << 4);
                ldsm2t(a, bvh);
                ldsm2t(a + (OVL - OVH), bvl);
                mma_bf16(oacc[nv], pah, bvh);
                mma_bf16(oacc[nv], pah, bvl);
                mma_bf16(oacc[nv], pal, bvh);
            }
        }
    }

    // epilogue: normalize + split to bf16 hi/lo (feeds out-proj GEMM)
    float i0 = 1.f / l0, i1 = 1.f / l1;
    int row0 = q0 + r0 + g;
#pragma unroll
    for (int nv = 0; nv < 16; nv++) {
        int col = h * DVV + nv * 8 + 2 * t;
        unsigned hw, lw;
        packsplit(oacc[nv][0] * i0, oacc[nv][1] * i0, hw, lw);
        *(unsigned*)(Oh + (size_t)row0 * (HH * DVV) + col) = hw;
        *(unsigned*)(Ol + (size_t)row0 * (HH * DVV) + col) = lw;
        packsplit(oacc[nv][2] * i1, oacc[nv][3] * i1, hw, lw);
        *(unsigned*)(Oh + (size_t)(row0 + 8) * (HH * DVV) + col) = hw;
        *(unsigned*)(Ol + (size_t)(row0 + 8) * (HH * DVV) + col) = lw;
    }
}

// ======================= launch =======================
extern "C" void kernel_launch(void* const* d_in, const int* in_sizes, int n_in,
                              void* d_out, int out_size) {
    const float* x       = (const float*)d_in[0];
    const float* w_q_a   = (const float*)d_in[1];
    const float* q_a_ln  = (const float*)d_in[2];
    const float* w_q_b   = (const float*)d_in[3];
    const float* w_kv_a  = (const float*)d_in[4];
    const float* kv_a_ln = (const float*)d_in[5];
    const float* w_kv_b  = (const float*)d_in[6];
    const float* w_out   = (const float*)d_in[7];
    float* out = (float*)d_out;

    float *qa, *qbuf, *ckv;
    __nv_bfloat16 *Ah, *Al, *Bh, *Bl, *kvh, *kvl, *kpeh, *kpel;
    cudaGetSymbolAddress((void**)&qa,   g_qa);
    cudaGetSymbolAddress((void**)&qbuf, g_q);
    cudaGetSymbolAddress((void**)&ckv,  g_ckv);
    cudaGetSymbolAddress((void**)&Ah,   g_Ah);
    cudaGetSymbolAddress((void**)&Al,   g_Al);
    cudaGetSymbolAddress((void**)&Bh,   g_Bh);
    cudaGetSymbolAddress((void**)&Bl,   g_Bl);
    cudaGetSymbolAddress((void**)&kvh,  g_kvh);
    cudaGetSymbolAddress((void**)&kvl,  g_kvl);
    cudaGetSymbolAddress((void**)&kpeh, g_kpeh);
    cudaGetSymbolAddress((void**)&kpel, g_kpel);

    cudaFuncSetAttribute(bgemm2, cudaFuncAttributeMaxDynamicSharedMemorySize, BG_SMEM);
    cudaFuncSetAttribute(flash2, cudaFuncAttributeMaxDynamicSharedMemorySize, FL2_SMEM);

    dim3 blk(256);
    auto conv = [&](const float* src, __nv_bfloat16* h, __nv_bfloat16* l, int n) {
        conv_split<<<(n / 8 + 255) / 256, blk>>>(src, h, l, n);
    };
    auto gemm = [&](float* c, int N, int K) {
        bgemm2<<<dim3((N + 127) / 128, SQ / 128), blk, BG_SMEM>>>(
            Ah, Al, Bh, Bl, c, nullptr, nullptr, N, K, 0);
    };

    // x -> bf16 hi/lo (A side for q_a and kv_a gemms)
    conv(x, Ah, Al, SQ * EE);

    // 1. q_a = x @ w_q_a [2048,2048]x[2048,1536]
    conv(w_q_a, Bh, Bl, EE * QLR);
    gemm(qa, QLR, EE);

    // 2. ckv = x @ w_kv_a [2048,2048]x[2048,576]
    conv(w_kv_a, Bh, Bl, EE * (KLR + DRR));
    gemm(ckv, KLR + DRR, EE);

    // 3. rope_k (reads ckv fp32) -> split kpe
    rope_k_split<<<(SQ * 32 + 255) / 256, blk>>>(ckv, kpeh, kpel);

    // 4. rmsnorm(qa) -> Ah/Al ; q = qa_n @ w_q_b [2048,1536]x[1536,3072]
    rmsnorm_split<<<SQ, blk>>>(qa, q_a_ln, Ah, Al, QLR, QLR);
    conv(w_q_b, Bh, Bl, QLR * HH * DQQ);
    gemm(qbuf, HH * DQQ, QLR);

    // 5. rmsnorm(ckv) -> Ah/Al ; kv = ckv_n @ w_kv_b (split epilogue -> kvh/kvl)
    rmsnorm_split<<<SQ, blk>>>(ckv, kv_a_ln, Ah, Al, KLR, KLR + DRR);
    conv(w_kv_b, Bh, Bl, KLR * HH * 256);
    bgemm2<<<dim3((HH * 256) / 128, SQ / 128), blk, BG_SMEM>>>(
        Ah, Al, Bh, Bl, nullptr, kvh, kvl, HH * 256, KLR, 1);

    // 6. rope q (in place fp32)
    rope_q_kernel<<<(SQ * HH * 32) / 256, blk>>>(qbuf);

    // 7. attention -> writes split O into Ah/Al
    flash2<<<dim3(SQ / 128, HH), blk, FL2_SMEM>>>(qbuf, kvh, kvl, kpeh, kpel, Ah, Al);

    // 8. out = o @ w_out [2048,2048]x[2048,2048]
    conv(w_out, Bh, Bl, HH * DVV * EE);
    gemm(out, EE, HH * DVV);
}

// round 7
// speedup vs baseline: 4.8144x; 1.0927x over previous
#include <cuda_runtime.h>
#include <cuda_bf16.h>
#include <math.h>
#include <stdint.h>

#define SQ   2048
#define EE   2048
#define HH   16
#define QLR  1536
#define KLR  512
#define DNN  128
#define DRR  64
#define DVV  128
#define DQQ  192
#define N1C  2176   // padded combined N for gemm1 (1536 + 576 -> 17*128)

// -------- scratch --------
__device__ float g_c1  [SQ * N1C];          // [qa(1536) | ckv(512) | kpe_raw(64) | pad]
__device__ float g_q   [SQ * HH * DQQ];

__device__ __nv_bfloat16 g_Ah [SQ * EE];
__device__ __nv_bfloat16 g_Al [SQ * EE];
__device__ __nv_bfloat16 g_Bh [QLR * 3072];
__device__ __nv_bfloat16 g_Bl [QLR * 3072];
__device__ __nv_bfloat16 g_kvh[SQ * HH * 256];
__device__ __nv_bfloat16 g_kvl[SQ * HH * 256];
__device__ __nv_bfloat16 g_kpeh[SQ * DRR];
__device__ __nv_bfloat16 g_kpel[SQ * DRR];

// ======================= helpers =======================
__device__ __forceinline__ uint32_t s2u(const void* p) {
    return (uint32_t)__cvta_generic_to_shared(p);
}
__device__ __forceinline__ void cpa(uint32_t d, const void* s) {
    asm volatile("cp.async.cg.shared.global [%0], [%1], 16;\n" :: "r"(d), "l"(s));
}
#define CP_COMMIT asm volatile("cp.async.commit_group;\n")
#define CP_WAIT0  asm volatile("cp.async.wait_group 0;\n")
#define CP_WAIT1  asm volatile("cp.async.wait_group 1;\n")
#define CP_WAIT2  asm volatile("cp.async.wait_group 2;\n")

__device__ __forceinline__ void ldsm4(uint32_t a, unsigned* d) {
    asm volatile("ldmatrix.sync.aligned.m8n8.x4.shared.b16 {%0,%1,%2,%3}, [%4];\n"
        : "=r"(d[0]), "=r"(d[1]), "=r"(d[2]), "=r"(d[3]) : "r"(a));
}
__device__ __forceinline__ void ldsm2(uint32_t a, unsigned* d) {
    asm volatile("ldmatrix.sync.aligned.m8n8.x2.shared.b16 {%0,%1}, [%2];\n"
        : "=r"(d[0]), "=r"(d[1]) : "r"(a));
}
__device__ __forceinline__ void ldsm2t(uint32_t a, unsigned* d) {
    asm volatile("ldmatrix.sync.aligned.m8n8.x2.trans.shared.b16 {%0,%1}, [%2];\n"
        : "=r"(d[0]), "=r"(d[1]) : "r"(a));
}
__device__ __forceinline__ void mma_bf16(float* d, const unsigned* a, const unsigned* b) {
    asm volatile(
        "mma.sync.aligned.m16n8k16.row.col.f32.bf16.bf16.f32 "
        "{%0,%1,%2,%3}, {%4,%5,%6,%7}, {%8,%9}, {%0,%1,%2,%3};\n"
        : "+f"(d[0]), "+f"(d[1]), "+f"(d[2]), "+f"(d[3])
        : "r"(a[0]), "r"(a[1]), "r"(a[2]), "r"(a[3]), "r"(b[0]), "r"(b[1]));
}
__device__ __forceinline__ unsigned short bfu(__nv_bfloat16 v) {
    return *(unsigned short*)&v;
}
__device__ __forceinline__ void packsplit(float x, float y, unsigned& h, unsigned& l) {
    __nv_bfloat16 xh = __float2bfloat16(x), yh = __float2bfloat16(y);
    __nv_bfloat16 xl = __float2bfloat16(x - __bfloat162float(xh));
    __nv_bfloat16 yl = __float2bfloat16(y - __bfloat162float(yh));
    h = (unsigned)bfu(xh) | ((unsigned)bfu(yh) << 16);
    l = (unsigned)bfu(xl) | ((unsigned)bfu(yl) << 16);
}
__device__ __forceinline__ void split8(const float* f, uint4& hv, uint4& lv) {
    unsigned hw[4], lw[4];
#pragma unroll
    for (int j = 0; j < 4; j++) packsplit(f[2 * j], f[2 * j + 1], hw[j], lw[j]);
    hv = make_uint4(hw[0], hw[1], hw[2], hw[3]);
    lv = make_uint4(lw[0], lw[1], lw[2], lw[3]);
}

// ======================= fp32 -> bf16 hi/lo split ===========================
__global__ void conv_split(const float* __restrict__ in,
                           __nv_bfloat16* __restrict__ hi,
                           __nv_bfloat16* __restrict__ lo, int n) {
    int i = (blockIdx.x * blockDim.x + threadIdx.x) * 8;
    if (i >= n) return;
    float f[8];
    *(float4*)&f[0] = *(const float4*)(in + i);
    *(float4*)&f[4] = *(const float4*)(in + i + 4);
    uint4 hv, lv;
    split8(f, hv, lv);
    *(uint4*)(hi + i) = hv;
    *(uint4*)(lo + i) = lv;
}

// strided-dest variant: scatter [K,Nin] into combined [K,Nstr] at colOff
__global__ void conv_splitN(const float* __restrict__ in,
                            __nv_bfloat16* __restrict__ hi,
                            __nv_bfloat16* __restrict__ lo,
                            int Nin, int colOff, int Nstr, int n) {
    int i = (blockIdx.x * blockDim.x + threadIdx.x) * 8;
    if (i >= n) return;
    int r = i / Nin, c = i % Nin;
    float f[8];
    *(float4*)&f[0] = *(const float4*)(in + i);
    *(float4*)&f[4] = *(const float4*)(in + i + 4);
    uint4 hv, lv;
    split8(f, hv, lv);
    size_t o = (size_t)r * Nstr + colOff + c;
    *(uint4*)(hi + o) = hv;
    *(uint4*)(lo + o) = lv;
}

// ======================= RMSNorm fused with split ===========================
__global__ void rmsnorm_split(const float* __restrict__ in,
                              const float* __restrict__ w,
                              __nv_bfloat16* __restrict__ hi,
                              __nv_bfloat16* __restrict__ lo,
                              int D, int in_stride) {
    const int row = blockIdx.x;
    const float* x = in + (size_t)row * in_stride;
    float ss = 0.f;
    for (int i = threadIdx.x; i < D; i += blockDim.x) { float v = x[i]; ss += v * v; }
#pragma unroll
    for (int m = 16; m; m >>= 1) ss += __shfl_xor_sync(0xffffffffu, ss, m);
    __shared__ float wsum[8];
    if ((threadIdx.x & 31) == 0) wsum[threadIdx.x >> 5] = ss;
    __syncthreads();
    float tot = 0.f;
#pragma unroll
    for (int i = 0; i < 8; i++) tot += wsum[i];
    float scale = rsqrtf(tot / (float)D + 1e-6f);
    for (int i = threadIdx.x; i < D; i += blockDim.x) {
        float v = x[i] * scale * w[i];
        __nv_bfloat16 h = __float2bfloat16(v);
        __nv_bfloat16 l = __float2bfloat16(v - __bfloat162float(h));
        hi[(size_t)row * D + i] = h;
        lo[(size_t)row * D + i] = l;
    }
}

// ======================= bgemm2: 3-stage cp.async + ldmatrix ================
#define BG_STAGE 32768
#define BG_SMEM  (3 * BG_STAGE)

__global__ __launch_bounds__(256, 2) void bgemm2(const __nv_bfloat16* __restrict__ Ahg,
                                                 const __nv_bfloat16* __restrict__ Alg,
                                                 const __nv_bfloat16* __restrict__ Bhg,
                                                 const __nv_bfloat16* __restrict__ Blg,
                                                 float* __restrict__ C,
                                                 __nv_bfloat16* __restrict__ Ch,
                                                 __nv_bfloat16* __restrict__ Cl,
                                                 int N, int K, int mode) {
    extern __shared__ char smem[];
    const uint32_t sb = s2u(smem);
    const int tid = threadIdx.x;
    const int lane = tid & 31, warp = tid >> 5;
    const int wm = warp >> 2, wn = warp & 3;
    const int g = lane >> 2, t = lane & 3;
    const int bm = blockIdx.y * 128, bn = blockIdx.x * 128;

    float acc[4][4][4];
#pragma unroll
    for (int mt = 0; mt < 4; mt++)
#pragma unroll
        for (int nt = 0; nt < 4; nt++)
#pragma unroll
            for (int k = 0; k < 4; k++) acc[mt][nt][k] = 0.f;

    const int nsteps = K >> 5;

    auto load_stage = [&](int s) {
        uint32_t base = sb + (s % 3) * BG_STAGE;
        int k0 = s << 5;
#pragma unroll
        for (int p = 0; p < 2; p++) {
            int id = tid + p * 256;
            int r = id >> 2, sg = id & 3;
            uint32_t dst = base + r * 64 + (((sg ^ ((r >> 1) & 3))) << 4);
            size_t go = (size_t)(bm + r) * K + k0 + sg * 8;
            cpa(dst, Ahg + go);
            cpa(dst + 8192, Alg + go);
        }
#pragma unroll
        for (int p = 0; p < 2; p++) {
            int id = tid + p * 256;
            int r = id >> 4, sg = id & 15;
            uint32_t dst = base + 16384 + r * 256 + ((sg ^ (r & 7)) << 4);
            size_t go = (size_t)(k0 + r) * N + bn + sg * 8;
            cpa(dst, Bhg + go);
            cpa(dst + 8192, Blg + go);
        }
        CP_COMMIT;
    };

    load_stage(0);
    if (nsteps > 1) load_stage(1);

    for (int s = 0; s < nsteps; s++) {
        if (s + 2 < nsteps) {
            load_stage(s + 2);
            CP_WAIT2;
        } else if (s + 1 < nsteps) {
            CP_WAIT1;
        } else {
            CP_WAIT0;
        }
        __syncthreads();

        uint32_t ab = sb + (s % 3) * BG_STAGE;
        uint32_t bb = ab + 16384;
        const int lr = (lane & 7) + 8 * ((lane >> 3) & 1);

#pragma unroll
        for (int kk = 0; kk < 32; kk += 16) {
            unsigned ah[4][4], al[4][4], bh[4][2], bl[4][2];
            int sgA = (kk >> 3) + (lane >> 4);
#pragma unroll
            for (int mt = 0; mt < 4; mt++) {
                int row = wm * 64 + mt * 16 + lr;
                uint32_t a = ab + row * 64 + ((sgA ^ ((row >> 1) & 3)) << 4);
                ldsm4(a, ah[mt]);
                ldsm4(a + 8192, al[mt]);
            }
            int rB = kk + lr;
#pragma unroll
            for (int nt = 0; nt < 4; nt++) {
                int sgB = wn * 4 + nt;
                uint32_t b = bb + rB * 256 + ((sgB ^ (rB & 7)) << 4);
                ldsm2t(b, bh[nt]);
                ldsm2t(b + 8192, bl[nt]);
            }
#pragma unroll
            for (int mt = 0; mt < 4; mt++)
#pragma unroll
                for (int nt = 0; nt < 4; nt++) {
                    mma_bf16(acc[mt][nt], ah[mt], bh[nt]);
                    mma_bf16(acc[mt][nt], ah[mt], bl[nt]);
                    mma_bf16(acc[mt][nt], al[mt], bh[nt]);
                }
        }
        __syncthreads();
    }

    if (mode == 0) {
#pragma unroll
        for (int mt = 0; mt < 4; mt++) {
            int row = bm + wm * 64 + mt * 16 + g;
#pragma unroll
            for (int nt = 0; nt < 4; nt++) {
                int col = bn + wn * 32 + nt * 8 + 2 * t;
                if (col < N) {
                    *(float2*)&C[(size_t)row * N + col] =
                        make_float2(acc[mt][nt][0], acc[mt][nt][1]);
                    *(float2*)&C[(size_t)(row + 8) * N + col] =
                        make_float2(acc[mt][nt][2], acc[mt][nt][3]);
                }
            }
        }
    } else {
#pragma unroll
        for (int mt = 0; mt < 4; mt++) {
            int row = bm + wm * 64 + mt * 16 + g;
#pragma unroll
            for (int nt = 0; nt < 4; nt++) {
                int col = bn + wn * 32 + nt * 8 + 2 * t;
                unsigned hw, lw;
                packsplit(acc[mt][nt][0], acc[mt][nt][1], hw, lw);
                *(unsigned*)(Ch + (size_t)row * N + col) = hw;
                *(unsigned*)(Cl + (size_t)row * N + col) = lw;
                packsplit(acc[mt][nt][2], acc[mt][nt][3], hw, lw);
                *(unsigned*)(Ch + (size_t)(row + 8) * N + col) = hw;
                *(unsigned*)(Cl + (size_t)(row + 8) * N + col) = lw;
            }
        }
    }
}

// ======================= RoPE-K (reads combined c1) ========================
#define LOG2_10000_OVER_32 0.4152410118609203f

__global__ void rope_k_split(const float* __restrict__ src, int stride,
                             __nv_bfloat16* __restrict__ kpeh,
                             __nv_bfloat16* __restrict__ kpel) {
    int w = (blockIdx.x * blockDim.x + threadIdx.x) >> 5;
    int lane = threadIdx.x & 31;
    if (w >= SQ) return;
    const float* base = src + (size_t)w * stride;
    float x0 = base[2 * lane];
    float x1 = base[2 * lane + 1];
    float invf = exp2f(-(float)lane * LOG2_10000_OVER_32);
    float ang = (float)w * invf;
    float sn, cs;
    sincosf(ang, &sn, &cs);
    float o0 = x0 * cs - x1 * sn;
    float o1 = x1 * cs + x0 * sn;
    __nv_bfloat16 h0 = __float2bfloat16(o0);
    __nv_bfloat16 h1 = __float2bfloat16(o1);
    kpeh[(size_t)w * DRR + lane]      = h0;
    kpeh[(size_t)w * DRR + 32 + lane] = h1;
    kpel[(size_t)w * DRR + lane]      = __float2bfloat16(o0 - __bfloat162float(h0));
    kpel[(size_t)w * DRR + 32 + lane] = __float2bfloat16(o1 - __bfloat162float(h1));
}

// ======================= flash2: tensor-core flash attention ================
// BM=128, BN=64. Q rope fused at load. K double-buffered prefetch, V deferred.
// smem: QH 0..48K, QL 48K..96K, K buffers 96K + b*48K (Kh 24K, Kl 24K),
//       VH 192K..208K, VL 208K..224K.  Total 229376 B.
#define OQH 0
#define OQL 49152
#define OKB(b) (98304 + (b) * 49152)
#define OVH 196608
#define OVL 212992
#define FL2_SMEM 229376

__global__ __launch_bounds__(256, 1) void flash2(const float* __restrict__ q,
                                                 const __nv_bfloat16* __restrict__ kvh,
                                                 const __nv_bfloat16* __restrict__ kvl,
                                                 const __nv_bfloat16* __restrict__ kpeh,
                                                 const __nv_bfloat16* __restrict__ kpel,
                                                 __nv_bfloat16* __restrict__ Oh,
                                                 __nv_bfloat16* __restrict__ Ol) {
    extern __shared__ char smem[];
    const uint32_t sb = s2u(smem);
    const int tid = threadIdx.x, lane = tid & 31, warp = tid >> 5;
    const int g = lane >> 2, t = lane & 3;
    const int h = blockIdx.y;
    const int qb = gridDim.x - 1 - blockIdx.x;
    const int q0 = qb * 128;
    const int r0 = warp * 16;
    const float scale = 0.07216878364870322f;

    auto load_K = [&](int k0, int buf) {
        uint32_t kb_h = sb + OKB(buf);
        uint32_t kb_l = kb_h + 24576;
        for (int i = tid; i < 64 * 24; i += 256) {
            int r = i / 24, sg = i % 24;
            uint32_t off = r * 384 + ((sg ^ (r & 7)) << 4);
            if (sg < 16) {
                size_t go = (size_t)(k0 + r) * (HH * 256) + h * 256 + sg * 8;
                cpa(kb_h + off, kvh + go);
                cpa(kb_l + off, kvl + go);
            } else {
                size_t go = (size_t)(k0 + r) * DRR + (sg - 16) * 8;
                cpa(kb_h + off, kpeh + go);
                cpa(kb_l + off, kpel + go);
            }
        }
        CP_COMMIT;
    };
    auto load_V = [&](int k0) {
        for (int i = tid; i < 64 * 16; i += 256) {
            int r = i / 16, sg = i % 16;
            uint32_t off = r * 256 + ((sg ^ (r & 7)) << 4);
            size_t go = (size_t)(k0 + r) * (HH * 256) + h * 256 + DNN + sg * 8;
            cpa(sb + OVH + off, kvh + go);
            cpa(sb + OVL + off, kvl + go);
        }
        CP_COMMIT;
    };

    // prefetch K[0]
    load_K(0, 0);

    // ---- Q load with fused RoPE + split ----
    for (int i = tid; i < 128 * 24; i += 256) {
        int r = i / 24, sg = i % 24;
        int qrow = q0 + r;
        const float* qr = q + (size_t)qrow * (HH * DQQ) + h * DQQ;
        float f[8];
        if (sg < 16) {
            *(float4*)&f[0] = *(const float4*)(qr + sg * 8);
            *(float4*)&f[4] = *(const float4*)(qr + sg * 8 + 4);
        } else {
            int u_base = (sg - 16) * 8;          // 0..56
            int j_base = u_base & 31;
            float f2[16];
            const float* pe = qr + DNN + 2 * j_base;
#pragma unroll
            for (int v = 0; v < 4; v++) *(float4*)&f2[4 * v] = *(const float4*)(pe + 4 * v);
#pragma unroll
            for (int j2 = 0; j2 < 8; j2++) {
                int j = j_base + j2;
                float x0 = f2[2 * j2], x1 = f2[2 * j2 + 1];
                float invf = exp2f(-(float)j * LOG2_10000_OVER_32);
                float sn, cs;
                sincosf((float)qrow * invf, &sn, &cs);
                f[j2] = (u_base < 32) ? (x0 * cs - x1 * sn) : (x1 * cs + x0 * sn);
            }
        }
        uint4 hv, lv;
        split8(f, hv, lv);
        uint32_t off = r * 384 + ((sg ^ (r & 7)) << 4);
        *(uint4*)(smem + OQH + off) = hv;
        *(uint4*)(smem + OQL + off) = lv;
    }

    float m0 = -1e30f, m1 = -1e30f, l0 = 0.f, l1 = 0.f;
    float oacc[16][4];
#pragma unroll
    for (int nv = 0; nv < 16; nv++)
#pragma unroll
        for (int k = 0; k < 4; k++) oacc[nv][k] = 0.f;

    const int nkb = 2 * qb + 2;
    for (int kb = 0; kb < nkb; kb++) {
        const int k0 = kb * 64;
        const int cur = kb & 1;
        const bool pre = (kb + 1 < nkb);
        __syncthreads();               // V & K[next] buffers free of prior readers
        load_V(k0);
        if (pre) load_K(k0 + 64, cur ^ 1);
        if (pre) { CP_WAIT2; } else { CP_WAIT1; }   // K[kb] complete
        __syncthreads();

        // S = Q @ K^T
        float sacc[8][4];
#pragma unroll
        for (int nt = 0; nt < 8; nt++)
#pragma unroll
            for (int k = 0; k < 4; k++) sacc[nt][k] = 0.f;

        const uint32_t kb_h = sb + OKB(cur);
        const int lr = (lane & 7) + 8 * ((lane >> 3) & 1);
#pragma unroll
        for (int kk = 0; kk < 192; kk += 16) {
            unsigned ah[4], al[4];
            int rowA = r0 + lr;
            int sgA = (kk >> 3) + (lane >> 4);
            uint32_t a = sb + OQH + rowA * 384 + ((sgA ^ (rowA & 7)) << 4);
            ldsm4(a, ah);
            ldsm4(a + (OQL - OQH), al);
            int sgB = (kk >> 3) + ((lane >> 3) & 1);
#pragma unroll
            for (int nt = 0; nt < 8; nt++) {
                unsigned bh[2], bl[2];
                int rB = nt * 8 + (lane & 7);
                uint32_t b = kb_h + rB * 384 + ((sgB ^ (rB & 7)) << 4);
                ldsm2(b, bh);
                ldsm2(b + 24576, bl);
                mma_bf16(sacc[nt], ah, bh);
                mma_bf16(sacc[nt], ah, bl);
                mma_bf16(sacc[nt], al, bh);
            }
        }

        // mask + online softmax
        const int qi0 = q0 + r0 + g;
        const int qi1 = qi0 + 8;
        const bool full = (k0 + 63 <= q0 + r0);
        float mx0 = -1e30f, mx1 = -1e30f;
#pragma unroll
        for (int nt = 0; nt < 8; nt++) {
            int c = k0 + nt * 8 + 2 * t;
            float s00 = sacc[nt][0] * scale, s01 = sacc[nt][1] * scale;
            float s10 = sacc[nt][2] * scale, s11 = sacc[nt][3] * scale;
            if (!full) {
                if (c > qi0)     s00 = -1e30f;
                if (c + 1 > qi0) s01 = -1e30f;
                if (c > qi1)     s10 = -1e30f;
                if (c + 1 > qi1) s11 = -1e30f;
            }
            sacc[nt][0] = s00; sacc[nt][1] = s01;
            sacc[nt][2] = s10; sacc[nt][3] = s11;
            mx0 = fmaxf(mx0, fmaxf(s00, s01));
            mx1 = fmaxf(mx1, fmaxf(s10, s11));
        }
        mx0 = fmaxf(mx0, __shfl_xor_sync(0xffffffffu, mx0, 1));
        mx0 = fmaxf(mx0, __shfl_xor_sync(0xffffffffu, mx0, 2));
        mx1 = fmaxf(mx1, __shfl_xor_sync(0xffffffffu, mx1, 1));
        mx1 = fmaxf(mx1, __shfl_xor_sync(0xffffffffu, mx1, 2));

        float mn0 = fmaxf(m0, mx0), mn1 = fmaxf(m1, mx1);
        float a0 = __expf(m0 - mn0), a1 = __expf(m1 - mn1);
        float s0 = 0.f, s1 = 0.f;
#pragma unroll
        for (int nt = 0; nt < 8; nt++) {
            float p00 = __expf(sacc[nt][0] - mn0);
            float p01 = __expf(sacc[nt][1] - mn0);
            float p10 = __expf(sacc[nt][2] - mn1);
            float p11 = __expf(sacc[nt][3] - mn1);
            sacc[nt][0] = p00; sacc[nt][1] = p01;
            sacc[nt][2] = p10; sacc[nt][3] = p11;
            s0 += p00 + p01;
            s1 += p10 + p11;
        }
        s0 += __shfl_xor_sync(0xffffffffu, s0, 1);
        s0 += __shfl_xor_sync(0xffffffffu, s0, 2);
        s1 += __shfl_xor_sync(0xffffffffu, s1, 1);
        s1 += __shfl_xor_sync(0xffffffffu, s1, 2);
        l0 = l0 * a0 + s0;
        l1 = l1 * a1 + s1;
        m0 = mn0; m1 = mn1;
#pragma unroll
        for (int nv = 0; nv < 16; nv++) {
            oacc[nv][0] *= a0; oacc[nv][1] *= a0;
            oacc[nv][2] *= a1; oacc[nv][3] *= a1;
        }

        // V ready? (allow only K[next] outstanding)
        if (pre) { CP_WAIT1; } else { CP_WAIT0; }
        __syncthreads();

        // O += P @ V
#pragma unroll
        for (int u = 0; u < 4; u++) {
            unsigned pah[4], pal[4];
            packsplit(sacc[2 * u][0],     sacc[2 * u][1],     pah[0], pal[0]);
            packsplit(sacc[2 * u][2],     sacc[2 * u][3],     pah[1], pal[1]);
            packsplit(sacc[2 * u + 1][0], sacc[2 * u + 1][1], pah[2], pal[2]);
            packsplit(sacc[2 * u + 1][2], sacc[2 * u + 1][3], pah[3], pal[3]);
            int rV = u * 16 + lr;
#pragma unroll
            for (int nv = 0; nv < 16; nv++) {
                unsigned bvh[2], bvl[2];
                uint32_t a = sb + OVH + rV * 256 + ((nv ^ (rV & 7)) << 4);
                ldsm2t(a, bvh);
                ldsm2t(a + (OVL - OVH), bvl);
                mma_bf16(oacc[nv], pah, bvh);
                mma_bf16(oacc[nv], pah, bvl);
                mma_bf16(oacc[nv], pal, bvh);
            }
        }
    }

    // epilogue: normalize + split (feeds out-proj GEMM)
    float i0 = 1.f / l0, i1 = 1.f / l1;
    int row0 = q0 + r0 + g;
#pragma unroll
    for (int nv = 0; nv < 16; nv++) {
        int col = h * DVV + nv * 8 + 2 * t;
        unsigned hw, lw;
        packsplit(oacc[nv][0] * i0, oacc[nv][1] * i0, hw, lw);
        *(unsigned*)(Oh + (size_t)row0 * (HH * DVV) + col) = hw;
        *(unsigned*)(Ol + (size_t)row0 * (HH * DVV) + col) = lw;
        packsplit(oacc[nv][2] * i1, oacc[nv][3] * i1, hw, lw);
        *(unsigned*)(Oh + (size_t)(row0 + 8) * (HH * DVV) + col) = hw;
        *(unsigned*)(Ol + (size_t)(row0 + 8) * (HH * DVV) + col) = lw;
    }
}

// ======================= launch =======================
extern "C" void kernel_launch(void* const* d_in, const int* in_sizes, int n_in,
                              void* d_out, int out_size) {
    const float* x       = (const float*)d_in[0];
    const float* w_q_a   = (const float*)d_in[1];
    const float* q_a_ln  = (const float*)d_in[2];
    const float* w_q_b   = (const float*)d_in[3];
    const float* w_kv_a  = (const float*)d_in[4];
    const float* kv_a_ln = (const float*)d_in[5];
    const float* w_kv_b  = (const float*)d_in[6];
    const float* w_out   = (const float*)d_in[7];
    float* out = (float*)d_out;

    float *c1, *qbuf;
    __nv_bfloat16 *Ah, *Al, *Bh, *Bl, *kvh, *kvl, *kpeh, *kpel;
    cudaGetSymbolAddress((void**)&c1,   g_c1);
    cudaGetSymbolAddress((void**)&qbuf, g_q);
    cudaGetSymbolAddress((void**)&Ah,   g_Ah);
    cudaGetSymbolAddress((void**)&Al,   g_Al);
    cudaGetSymbolAddress((void**)&Bh,   g_Bh);
    cudaGetSymbolAddress((void**)&Bl,   g_Bl);
    cudaGetSymbolAddress((void**)&kvh,  g_kvh);
    cudaGetSymbolAddress((void**)&kvl,  g_kvl);
    cudaGetSymbolAddress((void**)&kpeh, g_kpeh);
    cudaGetSymbolAddress((void**)&kpel, g_kpel);

    cudaFuncSetAttribute(bgemm2, cudaFuncAttributeMaxDynamicSharedMemorySize, BG_SMEM);
    cudaFuncSetAttribute(flash2, cudaFuncAttributeMaxDynamicSharedMemorySize, FL2_SMEM);

    dim3 blk(256);
    auto conv = [&](const float* src, __nv_bfloat16* h, __nv_bfloat16* l, int n) {
        conv_split<<<(n / 8 + 255) / 256, blk>>>(src, h, l, n);
    };
    auto gemm = [&](float* c, int N, int K) {
        bgemm2<<<dim3((N + 127) / 128, SQ / 128), blk, BG_SMEM>>>(
            Ah, Al, Bh, Bl, c, nullptr, nullptr, N, K, 0);
    };

    // x -> Ah/Al
    conv(x, Ah, Al, SQ * EE);

    // merged gemm1: [x @ w_q_a | x @ w_kv_a] -> c1 [2048, 2176]
    conv_splitN<<<(EE * QLR / 8 + 255) / 256, blk>>>(w_q_a, Bh, Bl, QLR, 0, N1C, EE * QLR);
    conv_splitN<<<(EE * (KLR + DRR) / 8 + 255) / 256, blk>>>(
        w_kv_a, Bh, Bl, KLR + DRR, QLR, N1C, EE * (KLR + DRR));
    gemm(c1, N1C, EE);

    // rope k (cols 2048..2111 of c1)
    rope_k_split<<<(SQ * 32 + 255) / 256, blk>>>(c1 + QLR + KLR, N1C, kpeh, kpel);

    // rmsnorm(qa) -> Ah/Al ; q = qa_n @ w_q_b
    rmsnorm_split<<<SQ, blk>>>(c1, q_a_ln, Ah, Al, QLR, N1C);
    conv(w_q_b, Bh, Bl, QLR * HH * DQQ);
    gemm(qbuf, HH * DQQ, QLR);

    // rmsnorm(ckv) -> Ah/Al ; kv = ckv_n @ w_kv_b (split epilogue)
    rmsnorm_split<<<SQ, blk>>>(c1 + QLR, kv_a_ln, Ah, Al, KLR, N1C);
    conv(w_kv_b, Bh, Bl, KLR * HH * 256);
    bgemm2<<<dim3((HH * 256) / 128, SQ / 128), blk, BG_SMEM>>>(
        Ah, Al, Bh, Bl, nullptr, kvh, kvl, HH * 256, KLR, 1);

    // attention (rope_q fused) -> split O into Ah/Al
    flash2<<<dim3(SQ / 128, HH), blk, FL2_SMEM>>>(qbuf, kvh, kvl, kpeh, kpel, Ah, Al);

    // out = o @ w_out
    conv(w_out, Bh, Bl, HH * DVV * EE);
    gemm(out, EE, HH * DVV);
}

// round 8
// speedup vs baseline: 4.8678x; 1.0111x over previous
#include <cuda_runtime.h>
#include <cuda_bf16.h>
#include <math.h>
#include <stdint.h>

#define SQ   2048
#define EE   2048
#define HH   16
#define QLR  1536
#define KLR  512
#define DNN  128
#define DRR  64
#define DVV  128
#define DQQ  192
#define N1C  2176   // padded combined N for gemm1 (1536 + 576 -> 17*128)

// -------- scratch --------
__device__ float g_c1  [SQ * N1C];          // [qa(1536) | ckv(512) | kpe_raw(64) | pad]
__device__ float g_q   [SQ * HH * DQQ];

__device__ __nv_bfloat16 g_Ah [SQ * EE];
__device__ __nv_bfloat16 g_Al [SQ * EE];
__device__ __nv_bfloat16 g_Bh [QLR * 3072];
__device__ __nv_bfloat16 g_Bl [QLR * 3072];
__device__ __nv_bfloat16 g_kvh[SQ * HH * 256];
__device__ __nv_bfloat16 g_kvl[SQ * HH * 256];
__device__ __nv_bfloat16 g_kpeh[SQ * DRR];
__device__ __nv_bfloat16 g_kpel[SQ * DRR];

// ======================= helpers =======================
__device__ __forceinline__ uint32_t s2u(const void* p) {
    return (uint32_t)__cvta_generic_to_shared(p);
}
__device__ __forceinline__ void cpa(uint32_t d, const void* s) {
    asm volatile("cp.async.cg.shared.global [%0], [%1], 16;\n" :: "r"(d), "l"(s));
}
#define CP_COMMIT asm volatile("cp.async.commit_group;\n")
#define CP_WAIT0  asm volatile("cp.async.wait_group 0;\n")
#define CP_WAIT1  asm volatile("cp.async.wait_group 1;\n")
#define CP_WAIT2  asm volatile("cp.async.wait_group 2;\n")

__device__ __forceinline__ void ldsm4(uint32_t a, unsigned* d) {
    asm volatile("ldmatrix.sync.aligned.m8n8.x4.shared.b16 {%0,%1,%2,%3}, [%4];\n"
        : "=r"(d[0]), "=r"(d[1]), "=r"(d[2]), "=r"(d[3]) : "r"(a));
}
__device__ __forceinline__ void ldsm2(uint32_t a, unsigned* d) {
    asm volatile("ldmatrix.sync.aligned.m8n8.x2.shared.b16 {%0,%1}, [%2];\n"
        : "=r"(d[0]), "=r"(d[1]) : "r"(a));
}
__device__ __forceinline__ void ldsm2t(uint32_t a, unsigned* d) {
    asm volatile("ldmatrix.sync.aligned.m8n8.x2.trans.shared.b16 {%0,%1}, [%2];\n"
        : "=r"(d[0]), "=r"(d[1]) : "r"(a));
}
__device__ __forceinline__ void mma_bf16(float* d, const unsigned* a, const unsigned* b) {
    asm volatile(
        "mma.sync.aligned.m16n8k16.row.col.f32.bf16.bf16.f32 "
        "{%0,%1,%2,%3}, {%4,%5,%6,%7}, {%8,%9}, {%0,%1,%2,%3};\n"
        : "+f"(d[0]), "+f"(d[1]), "+f"(d[2]), "+f"(d[3])
        : "r"(a[0]), "r"(a[1]), "r"(a[2]), "r"(a[3]), "r"(b[0]), "r"(b[1]));
}
__device__ __forceinline__ unsigned short bfu(__nv_bfloat16 v) {
    return *(unsigned short*)&v;
}
__device__ __forceinline__ void packsplit(float x, float y, unsigned& h, unsigned& l) {
    __nv_bfloat16 xh = __float2bfloat16(x), yh = __float2bfloat16(y);
    __nv_bfloat16 xl = __float2bfloat16(x - __bfloat162float(xh));
    __nv_bfloat16 yl = __float2bfloat16(y - __bfloat162float(yh));
    h = (unsigned)bfu(xh) | ((unsigned)bfu(yh) << 16);
    l = (unsigned)bfu(xl) | ((unsigned)bfu(yl) << 16);
}
__device__ __forceinline__ void split8(const float* f, uint4& hv, uint4& lv) {
    unsigned hw[4], lw[4];
#pragma unroll
    for (int j = 0; j < 4; j++) packsplit(f[2 * j], f[2 * j + 1], hw[j], lw[j]);
    hv = make_uint4(hw[0], hw[1], hw[2], hw[3]);
    lv = make_uint4(lw[0], lw[1], lw[2], lw[3]);
}

// ======================= fp32 -> bf16 hi/lo split ===========================
__global__ void conv_split(const float* __restrict__ in,
                           __nv_bfloat16* __restrict__ hi,
                           __nv_bfloat16* __restrict__ lo, int n) {
    int i = (blockIdx.x * blockDim.x + threadIdx.x) * 8;
    if (i >= n) return;
    float f[8];
    *(float4*)&f[0] = *(const float4*)(in + i);
    *(float4*)&f[4] = *(const float4*)(in + i + 4);
    uint4 hv, lv;
    split8(f, hv, lv);
    *(uint4*)(hi + i) = hv;
    *(uint4*)(lo + i) = lv;
}

// strided-dest variant: scatter [K,Nin] into combined [K,Nstr] at colOff
__global__ void conv_splitN(const float* __restrict__ in,
                            __nv_bfloat16* __restrict__ hi,
                            __nv_bfloat16* __restrict__ lo,
                            int Nin, int colOff, int Nstr, int n) {
    int i = (blockIdx.x * blockDim.x + threadIdx.x) * 8;
    if (i >= n) return;
    int r = i / Nin, c = i % Nin;
    float f[8];
    *(float4*)&f[0] = *(const float4*)(in + i);
    *(float4*)&f[4] = *(const float4*)(in + i + 4);
    uint4 hv, lv;
    split8(f, hv, lv);
    size_t o = (size_t)r * Nstr + colOff + c;
    *(uint4*)(hi + o) = hv;
    *(uint4*)(lo + o) = lv;
}

// ======================= RMSNorm fused with split ===========================
__global__ void rmsnorm_split(const float* __restrict__ in,
                              const float* __restrict__ w,
                              __nv_bfloat16* __restrict__ hi,
                              __nv_bfloat16* __restrict__ lo,
                              int D, int in_stride) {
    const int row = blockIdx.x;
    const float* x = in + (size_t)row * in_stride;
    float ss = 0.f;
    for (int i = threadIdx.x; i < D; i += blockDim.x) { float v = x[i]; ss += v * v; }
#pragma unroll
    for (int m = 16; m; m >>= 1) ss += __shfl_xor_sync(0xffffffffu, ss, m);
    __shared__ float wsum[8];
    if ((threadIdx.x & 31) == 0) wsum[threadIdx.x >> 5] = ss;
    __syncthreads();
    float tot = 0.f;
#pragma unroll
    for (int i = 0; i < 8; i++) tot += wsum[i];
    float scale = rsqrtf(tot / (float)D + 1e-6f);
    for (int i = threadIdx.x; i < D; i += blockDim.x) {
        float v = x[i] * scale * w[i];
        __nv_bfloat16 h = __float2bfloat16(v);
        __nv_bfloat16 l = __float2bfloat16(v - __bfloat162float(h));
        hi[(size_t)row * D + i] = h;
        lo[(size_t)row * D + i] = l;
    }
}

// ======================= bgemm2: 3-stage, single-barrier pipeline ===========
// step s: wait(stage s); sync; prefetch(s+2); compute(s)
// safety: prefetch(s+2) overwrites buf[(s-1)%3], whose readers (compute s-1)
// all passed this step's leading barrier; compute(s) reads buf[s%3], which no
// outstanding group (s+1, s+2) writes.
#define BG_STAGE 32768
#define BG_SMEM  (3 * BG_STAGE)

__global__ __launch_bounds__(256, 2) void bgemm2(const __nv_bfloat16* __restrict__ Ahg,
                                                 const __nv_bfloat16* __restrict__ Alg,
                                                 const __nv_bfloat16* __restrict__ Bhg,
                                                 const __nv_bfloat16* __restrict__ Blg,
                                                 float* __restrict__ C,
                                                 __nv_bfloat16* __restrict__ Ch,
                                                 __nv_bfloat16* __restrict__ Cl,
                                                 int N, int K, int mode) {
    extern __shared__ char smem[];
    const uint32_t sb = s2u(smem);
    const int tid = threadIdx.x;
    const int lane = tid & 31, warp = tid >> 5;
    const int wm = warp >> 2, wn = warp & 3;
    const int g = lane >> 2, t = lane & 3;
    const int bm = blockIdx.y * 128, bn = blockIdx.x * 128;

    float acc[4][4][4];
#pragma unroll
    for (int mt = 0; mt < 4; mt++)
#pragma unroll
        for (int nt = 0; nt < 4; nt++)
#pragma unroll
            for (int k = 0; k < 4; k++) acc[mt][nt][k] = 0.f;

    const int nsteps = K >> 5;

    auto load_stage = [&](int s) {
        uint32_t base = sb + (s % 3) * BG_STAGE;
        int k0 = s << 5;
#pragma unroll
        for (int p = 0; p < 2; p++) {
            int id = tid + p * 256;
            int r = id >> 2, sg = id & 3;
            uint32_t dst = base + r * 64 + (((sg ^ ((r >> 1) & 3))) << 4);
            size_t go = (size_t)(bm + r) * K + k0 + sg * 8;
            cpa(dst, Ahg + go);
            cpa(dst + 8192, Alg + go);
        }
#pragma unroll
        for (int p = 0; p < 2; p++) {
            int id = tid + p * 256;
            int r = id >> 4, sg = id & 15;
            uint32_t dst = base + 16384 + r * 256 + ((sg ^ (r & 7)) << 4);
            size_t go = (size_t)(k0 + r) * N + bn + sg * 8;
            cpa(dst, Bhg + go);
            cpa(dst + 8192, Blg + go);
        }
        CP_COMMIT;
    };

    load_stage(0);
    if (nsteps > 1) load_stage(1);

    for (int s = 0; s < nsteps; s++) {
        if (s + 1 < nsteps) { CP_WAIT1; } else { CP_WAIT0; }
        __syncthreads();
        if (s + 2 < nsteps) load_stage(s + 2);

        uint32_t ab = sb + (s % 3) * BG_STAGE;
        uint32_t bb = ab + 16384;
        const int lr = (lane & 7) + 8 * ((lane >> 3) & 1);

#pragma unroll
        for (int kk = 0; kk < 32; kk += 16) {
            unsigned ah[4][4], al[4][4], bh[4][2], bl[4][2];
            int sgA = (kk >> 3) + (lane >> 4);
#pragma unroll
            for (int mt = 0; mt < 4; mt++) {
                int row = wm * 64 + mt * 16 + lr;
                uint32_t a = ab + row * 64 + ((sgA ^ ((row >> 1) & 3)) << 4);
                ldsm4(a, ah[mt]);
                ldsm4(a + 8192, al[mt]);
            }
            int rB = kk + lr;
#pragma unroll
            for (int nt = 0; nt < 4; nt++) {
                int sgB = wn * 4 + nt;
                uint32_t b = bb + rB * 256 + ((sgB ^ (rB & 7)) << 4);
                ldsm2t(b, bh[nt]);
                ldsm2t(b + 8192, bl[nt]);
            }
#pragma unroll
            for (int mt = 0; mt < 4; mt++)
#pragma unroll
                for (int nt = 0; nt < 4; nt++) {
                    mma_bf16(acc[mt][nt], ah[mt], bh[nt]);
                    mma_bf16(acc[mt][nt], ah[mt], bl[nt]);
                    mma_bf16(acc[mt][nt], al[mt], bh[nt]);
                }
        }
    }

    if (mode == 0) {
#pragma unroll
        for (int mt = 0; mt < 4; mt++) {
            int row = bm + wm * 64 + mt * 16 + g;
#pragma unroll
            for (int nt = 0; nt < 4; nt++) {
                int col = bn + wn * 32 + nt * 8 + 2 * t;
                if (col < N) {
                    *(float2*)&C[(size_t)row * N + col] =
                        make_float2(acc[mt][nt][0], acc[mt][nt][1]);
                    *(float2*)&C[(size_t)(row + 8) * N + col] =
                        make_float2(acc[mt][nt][2], acc[mt][nt][3]);
                }
            }
        }
    } else {
#pragma unroll
        for (int mt = 0; mt < 4; mt++) {
            int row = bm + wm * 64 + mt * 16 + g;
#pragma unroll
            for (int nt = 0; nt < 4; nt++) {
                int col = bn + wn * 32 + nt * 8 + 2 * t;
                unsigned hw, lw;
                packsplit(acc[mt][nt][0], acc[mt][nt][1], hw, lw);
                *(unsigned*)(Ch + (size_t)row * N + col) = hw;
                *(unsigned*)(Cl + (size_t)row * N + col) = lw;
                packsplit(acc[mt][nt][2], acc[mt][nt][3], hw, lw);
                *(unsigned*)(Ch + (size_t)(row + 8) * N + col) = hw;
                *(unsigned*)(Cl + (size_t)(row + 8) * N + col) = lw;
            }
        }
    }
}

// ======================= RoPE-K (reads combined c1) ========================
#define LOG2_10000_OVER_32 0.4152410118609203f

__global__ void rope_k_split(const float* __restrict__ src, int stride,
                             __nv_bfloat16* __restrict__ kpeh,
                             __nv_bfloat16* __restrict__ kpel) {
    int w = (blockIdx.x * blockDim.x + threadIdx.x) >> 5;
    int lane = threadIdx.x & 31;
    if (w >= SQ) return;
    const float* base = src + (size_t)w * stride;
    float x0 = base[2 * lane];
    float x1 = base[2 * lane + 1];
    float invf = exp2f(-(float)lane * LOG2_10000_OVER_32);
    float ang = (float)w * invf;
    float sn, cs;
    sincosf(ang, &sn, &cs);
    float o0 = x0 * cs - x1 * sn;
    float o1 = x1 * cs + x0 * sn;
    __nv_bfloat16 h0 = __float2bfloat16(o0);
    __nv_bfloat16 h1 = __float2bfloat16(o1);
    kpeh[(size_t)w * DRR + lane]      = h0;
    kpeh[(size_t)w * DRR + 32 + lane] = h1;
    kpel[(size_t)w * DRR + lane]      = __float2bfloat16(o0 - __bfloat162float(h0));
    kpel[(size_t)w * DRR + 32 + lane] = __float2bfloat16(o1 - __bfloat162float(h1));
}

// ======================= flash2: tensor-core flash attention ================
// BM=128, BN=64. Q rope fused at load. K double-buffered prefetch, V deferred.
#define OQH 0
#define OQL 49152
#define OKB(b) (98304 + (b) * 49152)
#define OVH 196608
#define OVL 212992
#define FL2_SMEM 229376

__global__ __launch_bounds__(256, 1) void flash2(const float* __restrict__ q,
                                                 const __nv_bfloat16* __restrict__ kvh,
                                                 const __nv_bfloat16* __restrict__ kvl,
                                                 const __nv_bfloat16* __restrict__ kpeh,
                                                 const __nv_bfloat16* __restrict__ kpel,
                                                 __nv_bfloat16* __restrict__ Oh,
                                                 __nv_bfloat16* __restrict__ Ol) {
    extern __shared__ char smem[];
    const uint32_t sb = s2u(smem);
    const int tid = threadIdx.x, lane = tid & 31, warp = tid >> 5;
    const int g = lane >> 2, t = lane & 3;
    const int h = blockIdx.y;
    const int qb = gridDim.x - 1 - blockIdx.x;
    const int q0 = qb * 128;
    const int r0 = warp * 16;
    const float scale = 0.07216878364870322f;

    auto load_K = [&](int k0, int buf) {
        uint32_t kb_h = sb + OKB(buf);
        uint32_t kb_l = kb_h + 24576;
        for (int i = tid; i < 64 * 24; i += 256) {
            int r = i / 24, sg = i % 24;
            uint32_t off = r * 384 + ((sg ^ (r & 7)) << 4);
            if (sg < 16) {
                size_t go = (size_t)(k0 + r) * (HH * 256) + h * 256 + sg * 8;
                cpa(kb_h + off, kvh + go);
                cpa(kb_l + off, kvl + go);
            } else {
                size_t go = (size_t)(k0 + r) * DRR + (sg - 16) * 8;
                cpa(kb_h + off, kpeh + go);
                cpa(kb_l + off, kpel + go);
            }
        }
        CP_COMMIT;
    };
    auto load_V = [&](int k0) {
        for (int i = tid; i < 64 * 16; i += 256) {
            int r = i / 16, sg = i % 16;
            uint32_t off = r * 256 + ((sg ^ (r & 7)) << 4);
            size_t go = (size_t)(k0 + r) * (HH * 256) + h * 256 + DNN + sg * 8;
            cpa(sb + OVH + off, kvh + go);
            cpa(sb + OVL + off, kvl + go);
        }
        CP_COMMIT;
    };

    // prefetch K[0]
    load_K(0, 0);

    // ---- Q load with fused RoPE + split ----
    for (int i = tid; i < 128 * 24; i += 256) {
        int r = i / 24, sg = i % 24;
        int qrow = q0 + r;
        const float* qr = q + (size_t)qrow * (HH * DQQ) + h * DQQ;
        float f[8];
        if (sg < 16) {
            *(float4*)&f[0] = *(const float4*)(qr + sg * 8);
            *(float4*)&f[4] = *(const float4*)(qr + sg * 8 + 4);
        } else {
            int u_base = (sg - 16) * 8;
            int j_base = u_base & 31;
            float f2[16];
            const float* pe = qr + DNN + 2 * j_base;
#pragma unroll
            for (int v = 0; v < 4; v++) *(float4*)&f2[4 * v] = *(const float4*)(pe + 4 * v);
#pragma unroll
            for (int j2 = 0; j2 < 8; j2++) {
                int j = j_base + j2;
                float x0 = f2[2 * j2], x1 = f2[2 * j2 + 1];
                float invf = exp2f(-(float)j * LOG2_10000_OVER_32);
                float sn, cs;
                sincosf((float)qrow * invf, &sn, &cs);
                f[j2] = (u_base < 32) ? (x0 * cs - x1 * sn) : (x1 * cs + x0 * sn);
            }
        }
        uint4 hv, lv;
        split8(f, hv, lv);
        uint32_t off = r * 384 + ((sg ^ (r & 7)) << 4);
        *(uint4*)(smem + OQH + off) = hv;
        *(uint4*)(smem + OQL + off) = lv;
    }

    float m0 = -1e30f, m1 = -1e30f, l0 = 0.f, l1 = 0.f;
    float oacc[16][4];
#pragma unroll
    for (int nv = 0; nv < 16; nv++)
#pragma unroll
        for (int k = 0; k < 4; k++) oacc[nv][k] = 0.f;

    const int nkb = 2 * qb + 2;
    for (int kb = 0; kb < nkb; kb++) {
        const int k0 = kb * 64;
        const int cur = kb & 1;
        const bool pre = (kb + 1 < nkb);
        __syncthreads();
        load_V(k0);
        if (pre) load_K(k0 + 64, cur ^ 1);
        if (pre) { CP_WAIT2; } else { CP_WAIT1; }
        __syncthreads();

        // S = Q @ K^T
        float sacc[8][4];
#pragma unroll
        for (int nt = 0; nt < 8; nt++)
#pragma unroll
            for (int k = 0; k < 4; k++) sacc[nt][k] = 0.f;

        const uint32_t kb_h = sb + OKB(cur);
        const int lr = (lane & 7) + 8 * ((lane >> 3) & 1);
#pragma unroll
        for (int kk = 0; kk < 192; kk += 16) {
            unsigned ah[4], al[4];
            int rowA = r0 + lr;
            int sgA = (kk >> 3) + (lane >> 4);
            uint32_t a = sb + OQH + rowA * 384 + ((sgA ^ (rowA & 7)) << 4);
            ldsm4(a, ah);
            ldsm4(a + (OQL - OQH), al);
            int sgB = (kk >> 3) + ((lane >> 3) & 1);
#pragma unroll
            for (int nt = 0; nt < 8; nt++) {
                unsigned bh[2], bl[2];
                int rB = nt * 8 + (lane & 7);
                uint32_t b = kb_h + rB * 384 + ((sgB ^ (rB & 7)) << 4);
                ldsm2(b, bh);
                ldsm2(b + 24576, bl);
                mma_bf16(sacc[nt], ah, bh);
                mma_bf16(sacc[nt], ah, bl);
                mma_bf16(sacc[nt], al, bh);
            }
        }

        // mask + online softmax
        const int qi0 = q0 + r0 + g;
        const int qi1 = qi0 + 8;
        const bool full = (k0 + 63 <= q0 + r0);
        float mx0 = -1e30f, mx1 = -1e30f;
#pragma unroll
        for (int nt = 0; nt < 8; nt++) {
            int c = k0 + nt * 8 + 2 * t;
            float s00 = sacc[nt][0] * scale, s01 = sacc[nt][1] * scale;
            float s10 = sacc[nt][2] * scale, s11 = sacc[nt][3] * scale;
            if (!full) {
                if (c > qi0)     s00 = -1e30f;
                if (c + 1 > qi0) s01 = -1e30f;
                if (c > qi1)     s10 = -1e30f;
                if (c + 1 > qi1) s11 = -1e30f;
            }
            sacc[nt][0] = s00; sacc[nt][1] = s01;
            sacc[nt][2] = s10; sacc[nt][3] = s11;
            mx0 = fmaxf(mx0, fmaxf(s00, s01));
            mx1 = fmaxf(mx1, fmaxf(s10, s11));
        }
        mx0 = fmaxf(mx0, __shfl_xor_sync(0xffffffffu, mx0, 1));
        mx0 = fmaxf(mx0, __shfl_xor_sync(0xffffffffu, mx0, 2));
        mx1 = fmaxf(mx1, __shfl_xor_sync(0xffffffffu, mx1, 1));
        mx1 = fmaxf(mx1, __shfl_xor_sync(0xffffffffu, mx1, 2));

        float mn0 = fmaxf(m0, mx0), mn1 = fmaxf(m1, mx1);
        float a0 = __expf(m0 - mn0), a1 = __expf(m1 - mn1);
        float s0 = 0.f, s1 = 0.f;
#pragma unroll
        for (int nt = 0; nt < 8; nt++) {
            float p00 = __expf(sacc[nt][0] - mn0);
            float p01 = __expf(sacc[nt][1] - mn0);
            float p10 = __expf(sacc[nt][2] - mn1);
            float p11 = __expf(sacc[nt][3] - mn1);
            sacc[nt][0] = p00; sacc[nt][1] = p01;
            sacc[nt][2] = p10; sacc[nt][3] = p11;
            s0 += p00 + p01;
            s1 += p10 + p11;
        }
        s0 += __shfl_xor_sync(0xffffffffu, s0, 1);
        s0 += __shfl_xor_sync(0xffffffffu, s0, 2);
        s1 += __shfl_xor_sync(0xffffffffu, s1, 1);
        s1 += __shfl_xor_sync(0xffffffffu, s1, 2);
        l0 = l0 * a0 + s0;
        l1 = l1 * a1 + s1;
        m0 = mn0; m1 = mn1;
#pragma unroll
        for (int nv = 0; nv < 16; nv++) {
            oacc[nv][0] *= a0; oacc[nv][1] *= a0;
            oacc[nv][2] *= a1; oacc[nv][3] *= a1;
        }

        if (pre) { CP_WAIT1; } else { CP_WAIT0; }
        __syncthreads();

        // O += P @ V
#pragma unroll
        for (int u = 0; u < 4; u++) {
            unsigned pah[4], pal[4];
            packsplit(sacc[2 * u][0],     sacc[2 * u][1],     pah[0], pal[0]);
            packsplit(sacc[2 * u][2],     sacc[2 * u][3],     pah[1], pal[1]);
            packsplit(sacc[2 * u + 1][0], sacc[2 * u + 1][1], pah[2], pal[2]);
            packsplit(sacc[2 * u + 1][2], sacc[2 * u + 1][3], pah[3], pal[3]);
            int rV = u * 16 + lr;
#pragma unroll
            for (int nv = 0; nv < 16; nv++) {
                unsigned bvh[2], bvl[2];
                uint32_t a = sb + OVH + rV * 256 + ((nv ^ (rV & 7)) << 4);
                ldsm2t(a, bvh);
                ldsm2t(a + (OVL - OVH), bvl);
                mma_bf16(oacc[nv], pah, bvh);
                mma_bf16(oacc[nv], pah, bvl);
                mma_bf16(oacc[nv], pal, bvh);
            }
        }
    }

    // epilogue: normalize + split (feeds out-proj GEMM)
    float i0 = 1.f / l0, i1 = 1.f / l1;
    int row0 = q0 + r0 + g;
#pragma unroll
    for (int nv = 0; nv < 16; nv++) {
        int col = h * DVV + nv * 8 + 2 * t;
        unsigned hw, lw;
        packsplit(oacc[nv][0] * i0, oacc[nv][1] * i0, hw, lw);
        *(unsigned*)(Oh + (size_t)row0 * (HH * DVV) + col) = hw;
        *(unsigned*)(Ol + (size_t)row0 * (HH * DVV) + col) = lw;
        packsplit(oacc[nv][2] * i1, oacc[nv][3] * i1, hw, lw);
        *(unsigned*)(Oh + (size_t)(row0 + 8) * (HH * DVV) + col) = hw;
        *(unsigned*)(Ol + (size_t)(row0 + 8) * (HH * DVV) + col) = lw;
    }
}

// ======================= launch =======================
extern "C" void kernel_launch(void* const* d_in, const int* in_sizes, int n_in,
                              void* d_out, int out_size) {
    const float* x       = (const float*)d_in[0];
    const float* w_q_a   = (const float*)d_in[1];
    const float* q_a_ln  = (const float*)d_in[2];
    const float* w_q_b   = (const float*)d_in[3];
    const float* w_kv_a  = (const float*)d_in[4];
    const float* kv_a_ln = (const float*)d_in[5];
    const float* w_kv_b  = (const float*)d_in[6];
    const float* w_out   = (const float*)d_in[7];
    float* out = (float*)d_out;

    float *c1, *qbuf;
    __nv_bfloat16 *Ah, *Al, *Bh, *Bl, *kvh, *kvl, *kpeh, *kpel;
    cudaGetSymbolAddress((void**)&c1,   g_c1);
    cudaGetSymbolAddress((void**)&qbuf, g_q);
    cudaGetSymbolAddress((void**)&Ah,   g_Ah);
    cudaGetSymbolAddress((void**)&Al,   g_Al);
    cudaGetSymbolAddress((void**)&Bh,   g_Bh);
    cudaGetSymbolAddress((void**)&Bl,   g_Bl);
    cudaGetSymbolAddress((void**)&kvh,  g_kvh);
    cudaGetSymbolAddress((void**)&kvl,  g_kvl);
    cudaGetSymbolAddress((void**)&kpeh, g_kpeh);
    cudaGetSymbolAddress((void**)&kpel, g_kpel);

    cudaFuncSetAttribute(bgemm2, cudaFuncAttributeMaxDynamicSharedMemorySize, BG_SMEM);
    cudaFuncSetAttribute(flash2, cudaFuncAttributeMaxDynamicSharedMemorySize, FL2_SMEM);

    dim3 blk(256);
    auto conv = [&](const float* src, __nv_bfloat16* h, __nv_bfloat16* l, int n) {
        conv_split<<<(n / 8 + 255) / 256, blk>>>(src, h, l, n);
    };
    auto gemm = [&](float* c, int N, int K) {
        bgemm2<<<dim3((N + 127) / 128, SQ / 128), blk, BG_SMEM>>>(
            Ah, Al, Bh, Bl, c, nullptr, nullptr, N, K, 0);
    };

    // x -> Ah/Al
    conv(x, Ah, Al, SQ * EE);

    // merged gemm1: [x @ w_q_a | x @ w_kv_a] -> c1 [2048, 2176]
    conv_splitN<<<(EE * QLR / 8 + 255) / 256, blk>>>(w_q_a, Bh, Bl, QLR, 0, N1C, EE * QLR);
    conv_splitN<<<(EE * (KLR + DRR) / 8 + 255) / 256, blk>>>(
        w_kv_a, Bh, Bl, KLR + DRR, QLR, N1C, EE * (KLR + DRR));
    gemm(c1, N1C, EE);

    // rope k (cols 2048..2111 of c1)
    rope_k_split<<<(SQ * 32 + 255) / 256, blk>>>(c1 + QLR + KLR, N1C, kpeh, kpel);

    // rmsnorm(qa) -> Ah/Al ; q = qa_n @ w_q_b
    rmsnorm_split<<<SQ, blk>>>(c1, q_a_ln, Ah, Al, QLR, N1C);
    conv(w_q_b, Bh, Bl, QLR * HH * DQQ);
    gemm(qbuf, HH * DQQ, QLR);

    // rmsnorm(ckv) -> Ah/Al ; kv = ckv_n @ w_kv_b (split epilogue)
    rmsnorm_split<<<SQ, blk>>>(c1 + QLR, kv_a_ln, Ah, Al, KLR, N1C);
    conv(w_kv_b, Bh, Bl, KLR * HH * 256);
    bgemm2<<<dim3((HH * 256) / 128, SQ / 128), blk, BG_SMEM>>>(
        Ah, Al, Bh, Bl, nullptr, kvh, kvl, HH * 256, KLR, 1);

    // attention (rope_q fused) -> split O into Ah/Al
    flash2<<<dim3(SQ / 128, HH), blk, FL2_SMEM>>>(qbuf, kvh, kvl, kpeh, kpel, Ah, Al);

    // out = o @ w_out
    conv(w_out, Bh, Bl, HH * DVV * EE);
    gemm(out, EE, HH * DVV);
}